// round 10
// baseline (speedup 1.0000x reference)
#include <cuda_runtime.h>
#include <cuda_fp16.h>
#include <cstdint>

#define N_MAX 50000
#define E_MAX 1600000
#define ET_MAX (N_MAX + E_MAX)
#define FIN 128
#define F1 256
#define HID 64

#define NEG_SLOPE 0.2f
#define LN_EPS 1e-5f

// ------------------------- scratch (device globals; no allocation) ----------
__device__ __half g_xnh[(size_t)N_MAX * FIN];
__device__ __half g_w1t[(size_t)F1 * FIN];
__device__ __half g_w2t[(size_t)HID * F1];
__device__ __half g_xw1h[(size_t)N_MAX * F1];
__device__ float  g_as1[N_MAX * 4];
__device__ float  g_ad1[N_MAX * 4];
__device__ __half g_h2h[(size_t)N_MAX * F1];
__device__ __half g_xw2h[(size_t)N_MAX * HID];
__device__ float  g_as2[N_MAX];
__device__ float  g_ad2[N_MAX];
__device__ float  g_elg[N_MAX];
__device__ int    g_off[N_MAX + 1];
__device__ int    g_cnt[N_MAX];                  // zero-invariant across calls
__device__ int    g_cur[N_MAX];
__device__ int    g_csrc[ET_MAX];
__device__ float  g_rn[16];
__device__ int    g_bsum[64];
__device__ unsigned g_emax[10];
__device__ float  g_sumexp;

static __device__ __forceinline__ float lrelu(float x) { return x > 0.f ? x : NEG_SLOPE * x; }
static __device__ __forceinline__ float eluf(float x)  { return x > 0.f ? x : (__expf(x) - 1.f); }
static __device__ __forceinline__ unsigned encf(float x) {
    unsigned u = __float_as_uint(x);
    return (u & 0x80000000u) ? ~u : (u | 0x80000000u);
}
static __device__ __forceinline__ float dec_max(unsigned u) {
    return (u & 0x80000000u) ? __uint_as_float(u & 0x7fffffffu) : __uint_as_float(~u);
}
static __device__ __forceinline__ float4 h4f(uint2 u) {
    __half2 a = *(__half2*)&u.x;
    __half2 b = *(__half2*)&u.y;
    float2 fa = __half22float2(a), fb = __half22float2(b);
    return make_float4(fa.x, fa.y, fb.x, fb.y);
}

static __device__ __forceinline__ void ldsm4(unsigned* r, const void* p) {
    unsigned addr = (unsigned)__cvta_generic_to_shared(p);
    asm volatile("ldmatrix.sync.aligned.m8n8.x4.shared.b16 {%0,%1,%2,%3}, [%4];\n"
                 : "=r"(r[0]), "=r"(r[1]), "=r"(r[2]), "=r"(r[3]) : "r"(addr));
}
static __device__ __forceinline__ void mma16816f(float* d, const unsigned* a, const unsigned* b) {
    asm volatile(
        "mma.sync.aligned.m16n8k16.row.col.f32.f16.f16.f32 "
        "{%0,%1,%2,%3}, {%4,%5,%6,%7}, {%8,%9}, {%0,%1,%2,%3};\n"
        : "+f"(d[0]), "+f"(d[1]), "+f"(d[2]), "+f"(d[3])
        : "r"(a[0]), "r"(a[1]), "r"(a[2]), "r"(a[3]), "r"(b[0]), "r"(b[1]));
}

// ===================== stream A: rownorm || prepW || regime/zeros =============
#define PWB 192

__global__ void __launch_bounds__(256) k_phase1a(
    const float* __restrict__ x, const float* __restrict__ gamma,
    const float* __restrict__ beta,
    const float* __restrict__ reg, const float* __restrict__ rg,
    const float* __restrict__ rb,
    const float* __restrict__ W1, const float* __restrict__ W2,
    int n, int wb)
{
    int b = blockIdx.x;
    if (b < wb) {
        int wi = threadIdx.x >> 5;
        int l = threadIdx.x & 31;
        int w = b * 8 + wi;
        if (w >= n) return;
        float4 v = ((const float4*)(x + (size_t)w * FIN))[l];
        float s  = v.x + v.y + v.z + v.w;
        float ss = v.x*v.x + v.y*v.y + v.z*v.z + v.w*v.w;
#pragma unroll
        for (int off = 16; off; off >>= 1) {
            s  += __shfl_xor_sync(0xffffffffu, s, off);
            ss += __shfl_xor_sync(0xffffffffu, ss, off);
        }
        float mu = s * (1.f / FIN);
        float var = ss * (1.f / FIN) - mu * mu;
        float rstd = rsqrtf(var + LN_EPS);
        float4 g = ((const float4*)gamma)[l];
        float4 bb = ((const float4*)beta)[l];
        __half2 p0 = __floats2half2_rn((v.x - mu) * rstd * g.x + bb.x,
                                       (v.y - mu) * rstd * g.y + bb.y);
        __half2 p1 = __floats2half2_rn((v.z - mu) * rstd * g.z + bb.z,
                                       (v.w - mu) * rstd * g.w + bb.w);
        uint2 u; u.x = *(unsigned*)&p0; u.y = *(unsigned*)&p1;
        *(uint2*)(g_xnh + (size_t)w * FIN + 4 * l) = u;
    } else if (b < wb + PWB) {
        int i = (b - wb) * 256 + threadIdx.x;
        if (i < F1 * FIN) {
            int nn = i >> 7, kk = i & 127;
            g_w1t[i] = __float2half(W1[(size_t)kk * F1 + nn]);
        } else {
            int j = i - F1 * FIN;
            if (j < HID * F1) {
                int nn = j >> 8, kk = j & 255;
                g_w2t[j] = __float2half(W2[(size_t)kk * HID + nn]);
            }
        }
    } else {
        int t = threadIdx.x;
        if (t < 32) {
            float v = (t < 16) ? reg[t] : 0.f;
            float s = v, ss = v * v;
#pragma unroll
            for (int off = 16; off; off >>= 1) {
                s  += __shfl_xor_sync(0xffffffffu, s, off);
                ss += __shfl_xor_sync(0xffffffffu, ss, off);
            }
            float mu = s * (1.f / 16.f);
            float var = ss * (1.f / 16.f) - mu * mu;
            float rstd = rsqrtf(var + LN_EPS);
            if (t < 16) g_rn[t] = (v - mu) * rstd * rg[t] + rb[t];
        }
        if (t >= 32 && t < 42) g_emax[t - 32] = 0u;
        if (t == 42) g_sumexp = 0.f;
    }
}

// ===================== stream B: degree count =================================
__global__ void __launch_bounds__(256) k_count(const int* __restrict__ ei,
                                               int e, int etot) {
    int base = blockIdx.x * 1024 + threadIdx.x * 4;
    if (base + 3 < e) {
        int4 dd = *(const int4*)(ei + e + base);
        atomicAdd(&g_cnt[dd.x], 1);
        atomicAdd(&g_cnt[dd.y], 1);
        atomicAdd(&g_cnt[dd.z], 1);
        atomicAdd(&g_cnt[dd.w], 1);
    } else {
#pragma unroll
        for (int j = 0; j < 4; j++) {
            int i = base + j;
            if (i < etot) {
                int d = (i < e) ? ei[e + i] : (i - e);
                atomicAdd(&g_cnt[d], 1);
            }
        }
    }
}

__global__ void __launch_bounds__(256) k_scanA(int n) {
    __shared__ int ssc[256];
    int sb = blockIdx.x, tid = threadIdx.x;
    int base = sb * 1024 + tid * 4;
    int4 v = make_int4(0, 0, 0, 0);
    if (base + 3 < n) {
        v = *(const int4*)(g_cnt + base);
        *(int4*)(g_cnt + base) = make_int4(0, 0, 0, 0);
    } else {
        if (base     < n) { v.x = g_cnt[base];     g_cnt[base] = 0; }
        if (base + 1 < n) { v.y = g_cnt[base + 1]; g_cnt[base + 1] = 0; }
        if (base + 2 < n) { v.z = g_cnt[base + 2]; g_cnt[base + 2] = 0; }
    }
    int s = v.x + v.y + v.z + v.w;
    ssc[tid] = s;
    __syncthreads();
    for (int off = 1; off < 256; off <<= 1) {
        int u = (tid >= off) ? ssc[tid - off] : 0;
        __syncthreads();
        ssc[tid] += u;
        __syncthreads();
    }
    int excl = ssc[tid] - s;
    if (tid == 255) g_bsum[sb] = ssc[255];
    int4 o;
    o.x = excl; o.y = o.x + v.x; o.z = o.y + v.y; o.w = o.z + v.z;
    if (base + 3 < n) *(int4*)(g_off + base) = o;
    else {
        if (base     < n) g_off[base]     = o.x;
        if (base + 1 < n) g_off[base + 1] = o.y;
        if (base + 2 < n) g_off[base + 2] = o.z;
    }
}

__global__ void __launch_bounds__(256) k_scanC(int n, int etot) {
    __shared__ int sbp;
    int cb2 = blockIdx.x;
    int lane = threadIdx.x & 31;
    if (threadIdx.x < 32) {
        int s = 0;
        for (int j = lane; j < cb2; j += 32) s += g_bsum[j];
#pragma unroll
        for (int off = 16; off; off >>= 1) s += __shfl_xor_sync(0xffffffffu, s, off);
        if (lane == 0) sbp = s;
    }
    __syncthreads();
    int bpre = sbp;
    int base = cb2 * 1024 + threadIdx.x * 4;
    if (base + 3 < n) {
        int4 v = *(const int4*)(g_off + base);
        v.x += bpre; v.y += bpre; v.z += bpre; v.w += bpre;
        *(int4*)(g_off + base) = v;
        *(int4*)(g_cur + base) = v;
    } else {
#pragma unroll
        for (int j = 0; j < 4; j++) {
            int i = base + j;
            if (i < n) { int v = g_off[i] + bpre; g_off[i] = v; g_cur[i] = v; }
        }
    }
    if (cb2 == 0 && threadIdx.x == 0) g_off[n] = etot;
}

__global__ void __launch_bounds__(256) k_scatter(const int* __restrict__ ei,
                                                 int e, int etot) {
    int base = blockIdx.x * 1024 + threadIdx.x * 4;
    if (base + 3 < e) {
        int4 ssv = *(const int4*)(ei + base);
        int4 ddv = *(const int4*)(ei + e + base);
        g_csrc[atomicAdd(&g_cur[ddv.x], 1)] = ssv.x;
        g_csrc[atomicAdd(&g_cur[ddv.y], 1)] = ssv.y;
        g_csrc[atomicAdd(&g_cur[ddv.z], 1)] = ssv.z;
        g_csrc[atomicAdd(&g_cur[ddv.w], 1)] = ssv.w;
    } else {
#pragma unroll
        for (int j = 0; j < 4; j++) {
            int i = base + j;
            if (i < etot) {
                int s, d;
                if (i < e) { s = ei[i]; d = ei[e + i]; } else { s = d = i - e; }
                g_csrc[atomicAdd(&g_cur[d], 1)] = s;
            }
        }
    }
}

// ===================== GEMM1 (tensor cores) ===================================
__global__ void __launch_bounds__(256) k_hgemm1(const float* __restrict__ W1, int M)
{
    constexpr int BM = 128, BN = 128, BK = 64, WM = 64, WN = 32, K = FIN;
    constexpr int LDSM = BK + 8;
    __shared__ __align__(16) __half As[BM][LDSM];
    __shared__ __align__(16) __half Bs[BN][LDSM];
    __shared__ float cvs[BN];

    int b = blockIdx.x;
    int tid = threadIdx.x;
    int bx = b & 1, by = b >> 1;
    int wid = tid >> 5, lane = tid & 31;
    constexpr int NWN = BN / WN;
    int wm = wid / NWN, wn = wid % NWN;
    constexpr int MT = WM / 16, NT = WN / 8;
    int rb = by * BM, cb = bx * BN;
    int lr = lane & 7, grp = lane >> 3;

    if (tid < BN) {
        float s = 0.f;
#pragma unroll
        for (int k = 0; k < 16; k++)
            s += g_rn[k] * W1[(size_t)(FIN + k) * F1 + cb + tid];
        cvs[tid] = s;
    }

    float acc[MT][NT][4];
#pragma unroll
    for (int mt = 0; mt < MT; mt++)
#pragma unroll
        for (int nt = 0; nt < NT; nt++)
#pragma unroll
            for (int q = 0; q < 4; q++) acc[mt][nt][q] = 0.f;

    for (int k0 = 0; k0 < K; k0 += BK) {
        constexpr int AV = BM * BK / 8;
#pragma unroll
        for (int s = tid; s < AV; s += 256) {
            int row = s / (BK / 8), seg = s % (BK / 8);
            uint4 v = make_uint4(0u, 0u, 0u, 0u);
            if (rb + row < M) v = *(const uint4*)(g_xnh + (size_t)(rb + row) * K + k0 + seg * 8);
            *(uint4*)&As[row][seg * 8] = v;
        }
        constexpr int BV = BN * BK / 8;
#pragma unroll
        for (int s = tid; s < BV; s += 256) {
            int row = s / (BK / 8), seg = s % (BK / 8);
            *(uint4*)&Bs[row][seg * 8] = *(const uint4*)(g_w1t + (size_t)(cb + row) * K + k0 + seg * 8);
        }
        __syncthreads();
#pragma unroll
        for (int kk = 0; kk < BK; kk += 16) {
            unsigned a[MT][4], bfr[NT][2];
#pragma unroll
            for (int mt = 0; mt < MT; mt++) {
                int r = wm * WM + mt * 16 + (grp & 1) * 8 + lr;
                int c = kk + (grp >> 1) * 8;
                ldsm4(a[mt], &As[r][c]);
            }
#pragma unroll
            for (int np = 0; np < NT; np += 2) {
                int r = wn * WN + np * 8 + (grp >> 1) * 8 + lr;
                int c = kk + (grp & 1) * 8;
                unsigned t[4];
                ldsm4(t, &Bs[r][c]);
                bfr[np][0] = t[0]; bfr[np][1] = t[1];
                bfr[np + 1][0] = t[2]; bfr[np + 1][1] = t[3];
            }
#pragma unroll
            for (int mt = 0; mt < MT; mt++)
#pragma unroll
                for (int nt = 0; nt < NT; nt++)
                    mma16816f(acc[mt][nt], a[mt], bfr[nt]);
        }
        __syncthreads();
    }

    int qr = lane >> 2, qc = (lane & 3) * 2;
#pragma unroll
    for (int mt = 0; mt < MT; mt++)
#pragma unroll
        for (int nt = 0; nt < NT; nt++) {
            int row = rb + wm * WM + mt * 16 + qr;
            int lcol = wn * WN + nt * 8 + qc;
            int col = cb + lcol;
            float2 cv = *(const float2*)&cvs[lcol];
            if (row < M)
                *(__half2*)&g_xw1h[(size_t)row * F1 + col] =
                    __floats2half2_rn(acc[mt][nt][0] + cv.x, acc[mt][nt][1] + cv.y);
            if (row + 8 < M)
                *(__half2*)&g_xw1h[(size_t)(row + 8) * F1 + col] =
                    __floats2half2_rn(acc[mt][nt][2] + cv.x, acc[mt][nt][3] + cv.y);
        }
}

// ===================== alpha1 + per-head maxes ================================
__global__ void __launch_bounds__(256) k_alpha1(const float* __restrict__ asrc,
                                                const float* __restrict__ adst, int n)
{
    __shared__ float smax[8][8];
    int wi = threadIdx.x >> 5;
    int l = threadIdx.x & 31;
    int w = blockIdx.x * 8 + wi;
    const float NEGINF = -3.402823466e38f;
    float ps1 = NEGINF, ps2 = NEGINF, pd1 = NEGINF, pd2 = NEGINF;

    if (w < n) {
        const uint2* xr = (const uint2*)(g_xw1h + (size_t)w * F1);
        float4 x1 = h4f(xr[l]), x2 = h4f(xr[32 + l]);
        float4 s1 = ((const float4*)asrc)[l], s2 = ((const float4*)asrc)[32 + l];
        float4 d1 = ((const float4*)adst)[l], d2 = ((const float4*)adst)[32 + l];
        ps1 = x1.x*s1.x + x1.y*s1.y + x1.z*s1.z + x1.w*s1.w;
        ps2 = x2.x*s2.x + x2.y*s2.y + x2.z*s2.z + x2.w*s2.w;
        pd1 = x1.x*d1.x + x1.y*d1.y + x1.z*d1.z + x1.w*d1.w;
        pd2 = x2.x*d2.x + x2.y*d2.y + x2.z*d2.z + x2.w*d2.w;
#pragma unroll
        for (int off = 8; off; off >>= 1) {
            ps1 += __shfl_xor_sync(0xffffffffu, ps1, off);
            ps2 += __shfl_xor_sync(0xffffffffu, ps2, off);
            pd1 += __shfl_xor_sync(0xffffffffu, pd1, off);
            pd2 += __shfl_xor_sync(0xffffffffu, pd2, off);
        }
        if (l == 0)  { g_as1[w*4+0] = ps1; g_as1[w*4+2] = ps2; g_ad1[w*4+0] = pd1; g_ad1[w*4+2] = pd2; }
        if (l == 16) { g_as1[w*4+1] = ps1; g_as1[w*4+3] = ps2; g_ad1[w*4+1] = pd1; g_ad1[w*4+3] = pd2; }
    }
    if (l == 0)  { smax[0][wi] = ps1; smax[2][wi] = ps2; smax[4][wi] = pd1; smax[6][wi] = pd2; }
    if (l == 16) { smax[1][wi] = ps1; smax[3][wi] = ps2; smax[5][wi] = pd1; smax[7][wi] = pd2; }
    __syncthreads();
    if (threadIdx.x < 8) {
        float m = smax[threadIdx.x][0];
#pragma unroll
        for (int k = 1; k < 8; k++) m = fmaxf(m, smax[threadIdx.x][k]);
        if (m > -3.3e38f) atomicMax(&g_emax[threadIdx.x], encf(m));
    }
}

// -------------- GAT layer-1 aggregation (warp/dst, node range) -----------------
__global__ void __launch_bounds__(256) k_agg1(const float* __restrict__ b1,
                                              int nodeBase, int nodeEnd) {
    int w = nodeBase + ((blockIdx.x * blockDim.x + threadIdx.x) >> 5);
    int l = threadIdx.x & 31;
    if (w >= nodeEnd) return;
    int head = l >> 3;
    float adh = g_ad1[4 * w + head];
    float Mh = lrelu(dec_max(g_emax[head]) + dec_max(g_emax[4 + head]));
    int start = g_off[w], end = g_off[w + 1];

    float acc[8];
#pragma unroll
    for (int q = 0; q < 8; q++) acc[q] = 0.f;
    float den = 0.f;
    const __half* xw = g_xw1h;

    int i = start;
    for (; i + 4 <= end; i += 4) {
        int s0 = g_csrc[i], s1 = g_csrc[i + 1], s2 = g_csrc[i + 2], s3 = g_csrc[i + 3];
        float e0 = g_as1[4 * s0 + head];
        float e1 = g_as1[4 * s1 + head];
        float e2 = g_as1[4 * s2 + head];
        float e3 = g_as1[4 * s3 + head];
        uint4 x0 = *(const uint4*)(xw + (size_t)s0 * F1 + 8 * l);
        uint4 x1 = *(const uint4*)(xw + (size_t)s1 * F1 + 8 * l);
        uint4 x2 = *(const uint4*)(xw + (size_t)s2 * F1 + 8 * l);
        uint4 x3 = *(const uint4*)(xw + (size_t)s3 * F1 + 8 * l);
        float w0 = __expf(lrelu(e0 + adh) - Mh);
        float w1 = __expf(lrelu(e1 + adh) - Mh);
        float w2 = __expf(lrelu(e2 + adh) - Mh);
        float w3 = __expf(lrelu(e3 + adh) - Mh);
        den += (w0 + w1) + (w2 + w3);
        float4 a0 = h4f(make_uint2(x0.x, x0.y)), a1 = h4f(make_uint2(x0.z, x0.w));
        float4 c0 = h4f(make_uint2(x1.x, x1.y)), c1 = h4f(make_uint2(x1.z, x1.w));
        float4 d0 = h4f(make_uint2(x2.x, x2.y)), d1 = h4f(make_uint2(x2.z, x2.w));
        float4 f0 = h4f(make_uint2(x3.x, x3.y)), f1 = h4f(make_uint2(x3.z, x3.w));
        acc[0] += a0.x * w0 + c0.x * w1 + d0.x * w2 + f0.x * w3;
        acc[1] += a0.y * w0 + c0.y * w1 + d0.y * w2 + f0.y * w3;
        acc[2] += a0.z * w0 + c0.z * w1 + d0.z * w2 + f0.z * w3;
        acc[3] += a0.w * w0 + c0.w * w1 + d0.w * w2 + f0.w * w3;
        acc[4] += a1.x * w0 + c1.x * w1 + d1.x * w2 + f1.x * w3;
        acc[5] += a1.y * w0 + c1.y * w1 + d1.y * w2 + f1.y * w3;
        acc[6] += a1.z * w0 + c1.z * w1 + d1.z * w2 + f1.z * w3;
        acc[7] += a1.w * w0 + c1.w * w1 + d1.w * w2 + f1.w * w3;
    }
    for (; i < end; i++) {
        int s0 = g_csrc[i];
        float e0 = g_as1[4 * s0 + head];
        uint4 x0 = *(const uint4*)(xw + (size_t)s0 * F1 + 8 * l);
        float w0 = __expf(lrelu(e0 + adh) - Mh);
        den += w0;
        float4 a0 = h4f(make_uint2(x0.x, x0.y)), a1 = h4f(make_uint2(x0.z, x0.w));
        acc[0] += a0.x * w0; acc[1] += a0.y * w0;
        acc[2] += a0.z * w0; acc[3] += a0.w * w0;
        acc[4] += a1.x * w0; acc[5] += a1.y * w0;
        acc[6] += a1.z * w0; acc[7] += a1.w * w0;
    }
    float r = 1.f / den;
    const float* bp = b1 + 8 * l;
    float4 bb0 = *(const float4*)bp;
    float4 bb1 = *(const float4*)(bp + 4);
    __half2 q0 = __floats2half2_rn(eluf(acc[0] * r + bb0.x), eluf(acc[1] * r + bb0.y));
    __half2 q1 = __floats2half2_rn(eluf(acc[2] * r + bb0.z), eluf(acc[3] * r + bb0.w));
    __half2 q2 = __floats2half2_rn(eluf(acc[4] * r + bb1.x), eluf(acc[5] * r + bb1.y));
    __half2 q3 = __floats2half2_rn(eluf(acc[6] * r + bb1.z), eluf(acc[7] * r + bb1.w));
    uint4 st;
    st.x = *(unsigned*)&q0; st.y = *(unsigned*)&q1;
    st.z = *(unsigned*)&q2; st.w = *(unsigned*)&q3;
    *(uint4*)(g_h2h + (size_t)w * F1 + 8 * l) = st;
}

// ========== GEMM2 (tensor cores) + fused alpha2 dots + slot maxes =============
// Processes rows [rowBase, rowBase + gridDim.y*128) clipped to M.
__global__ void __launch_bounds__(256) k_hgemm2_a2(const float* __restrict__ asrc,
                                                   const float* __restrict__ adst,
                                                   int rowBase, int M)
{
    constexpr int BM = 128, BN = 64, BK = 64, WM = 32, WN = 32, K = F1;
    constexpr int LDSM = BK + 8;
    __shared__ __align__(16) __half As[BM][LDSM];
    __shared__ __align__(16) __half Bs[BN][LDSM];
    __shared__ float s_as[HID], s_ad[HID];
    __shared__ float s_p[BM], s_q[BM];

    int tid = threadIdx.x;
    int wid = tid >> 5, lane = tid & 31;
    constexpr int NWN = BN / WN;
    int wm = wid / NWN, wn = wid % NWN;
    constexpr int MT = WM / 16, NT = WN / 8;
    int rb = rowBase + blockIdx.y * BM, cb = 0;
    int lr = lane & 7, grp = lane >> 3;

    if (tid < HID) { s_as[tid] = asrc[tid]; s_ad[tid] = adst[tid]; }
    if (tid < BM)  { s_p[tid] = 0.f; s_q[tid] = 0.f; }

    float acc[MT][NT][4];
#pragma unroll
    for (int mt = 0; mt < MT; mt++)
#pragma unroll
        for (int nt = 0; nt < NT; nt++)
#pragma unroll
            for (int q = 0; q < 4; q++) acc[mt][nt][q] = 0.f;

    for (int k0 = 0; k0 < K; k0 += BK) {
        constexpr int AV = BM * BK / 8;
#pragma unroll
        for (int s = tid; s < AV; s += 256) {
            int row = s / (BK / 8), seg = s % (BK / 8);
            uint4 v = make_uint4(0u, 0u, 0u, 0u);
            if (rb + row < M) v = *(const uint4*)(g_h2h + (size_t)(rb + row) * K + k0 + seg * 8);
            *(uint4*)&As[row][seg * 8] = v;
        }
        constexpr int BV = BN * BK / 8;
#pragma unroll
        for (int s = tid; s < BV; s += 256) {
            int row = s / (BK / 8), seg = s % (BK / 8);
            *(uint4*)&Bs[row][seg * 8] = *(const uint4*)(g_w2t + (size_t)(cb + row) * K + k0 + seg * 8);
        }
        __syncthreads();
#pragma unroll
        for (int kk = 0; kk < BK; kk += 16) {
            unsigned a[MT][4], bfr[NT][2];
#pragma unroll
            for (int mt = 0; mt < MT; mt++) {
                int r = wm * WM + mt * 16 + (grp & 1) * 8 + lr;
                int c = kk + (grp >> 1) * 8;
                ldsm4(a[mt], &As[r][c]);
            }
#pragma unroll
            for (int np = 0; np < NT; np += 2) {
                int r = wn * WN + np * 8 + (grp >> 1) * 8 + lr;
                int c = kk + (grp & 1) * 8;
                unsigned t[4];
                ldsm4(t, &Bs[r][c]);
                bfr[np][0] = t[0]; bfr[np][1] = t[1];
                bfr[np + 1][0] = t[2]; bfr[np + 1][1] = t[3];
            }
#pragma unroll
            for (int mt = 0; mt < MT; mt++)
#pragma unroll
                for (int nt = 0; nt < NT; nt++)
                    mma16816f(acc[mt][nt], a[mt], bfr[nt]);
        }
        __syncthreads();
    }

    int qr = lane >> 2, qc = (lane & 3) * 2;
#pragma unroll
    for (int mt = 0; mt < MT; mt++) {
        float p0 = 0.f, q0v = 0.f, p1 = 0.f, q1v = 0.f;
#pragma unroll
        for (int nt = 0; nt < NT; nt++) {
            int col = wn * WN + nt * 8 + qc;
            float a0 = s_as[col], a1 = s_as[col + 1];
            float d0 = s_ad[col], d1 = s_ad[col + 1];
            p0  += acc[mt][nt][0] * a0 + acc[mt][nt][1] * a1;
            q0v += acc[mt][nt][0] * d0 + acc[mt][nt][1] * d1;
            p1  += acc[mt][nt][2] * a0 + acc[mt][nt][3] * a1;
            q1v += acc[mt][nt][2] * d0 + acc[mt][nt][3] * d1;
            int row = rb + wm * WM + mt * 16 + qr;
            if (row < M)
                *(__half2*)&g_xw2h[(size_t)row * HID + col] =
                    __floats2half2_rn(acc[mt][nt][0], acc[mt][nt][1]);
            if (row + 8 < M)
                *(__half2*)&g_xw2h[(size_t)(row + 8) * HID + col] =
                    __floats2half2_rn(acc[mt][nt][2], acc[mt][nt][3]);
        }
        int lrow = wm * WM + mt * 16 + qr;
        atomicAdd(&s_p[lrow], p0);
        atomicAdd(&s_q[lrow], q0v);
        atomicAdd(&s_p[lrow + 8], p1);
        atomicAdd(&s_q[lrow + 8], q1v);
    }
    __syncthreads();

    if (tid < BM) {
        int grow = rb + tid;
        float pv = s_p[tid], qv = s_q[tid];
        bool ok = (grow < M);
        if (ok) { g_as2[grow] = pv; g_ad2[grow] = qv; }
        float mp = ok ? pv : -3.402823466e38f;
        float mq = ok ? qv : -3.402823466e38f;
#pragma unroll
        for (int off = 16; off; off >>= 1) {
            mp = fmaxf(mp, __shfl_xor_sync(0xffffffffu, mp, off));
            mq = fmaxf(mq, __shfl_xor_sync(0xffffffffu, mq, off));
        }
        if ((tid & 31) == 0 && mp > -3.3e38f) atomicMax(&g_emax[8], encf(mp));
        if ((tid & 31) == 0 && mq > -3.3e38f) atomicMax(&g_emax[9], encf(mq));
    }
}

// ---- GAT layer-2 aggregation + fused logits + exp + sum ----------------------
__global__ void __launch_bounds__(256) k_agg2_logits(const float* __restrict__ b2,
                                                     const float* __restrict__ Wout,
                                                     const float* __restrict__ bout,
                                                     float* __restrict__ out, int n)
{
    __shared__ float sm[8];
    int wi = threadIdx.x >> 5;
    int l = threadIdx.x & 31;
    int w = blockIdx.x * 8 + wi;
    float elg = 0.f;

    if (w < n) {
        int start = g_off[w], end = g_off[w + 1];
        float adv = g_ad2[w];
        float M2 = lrelu(dec_max(g_emax[8]) + dec_max(g_emax[9]));

        float2 acc = make_float2(0.f, 0.f);
        float den = 0.f;
        int i = start;
        for (; i + 2 <= end; i += 2) {
            int s0 = g_csrc[i], s1 = g_csrc[i + 1];
            float e0 = __expf(lrelu(g_as2[s0] + adv) - M2);
            float e1 = __expf(lrelu(g_as2[s1] + adv) - M2);
            float2 x0 = __half22float2(*(const __half2*)&g_xw2h[(size_t)s0 * HID + 2 * l]);
            float2 x1 = __half22float2(*(const __half2*)&g_xw2h[(size_t)s1 * HID + 2 * l]);
            den += e0 + e1;
            acc.x += x0.x * e0 + x1.x * e1;
            acc.y += x0.y * e0 + x1.y * e1;
        }
        if (i < end) {
            int s0 = g_csrc[i];
            float e0 = __expf(lrelu(g_as2[s0] + adv) - M2);
            float2 x0 = __half22float2(*(const __half2*)&g_xw2h[(size_t)s0 * HID + 2 * l]);
            den += e0;
            acc.x += x0.x * e0;
            acc.y += x0.y * e0;
        }
        float r = 1.f / den;
        float2 bb = ((const float2*)b2)[l];
        float ox = eluf(acc.x * r + bb.x);
        float oy = eluf(acc.y * r + bb.y);
        float2 wv = ((const float2*)Wout)[l];
        float p = ox * wv.x + oy * wv.y;
#pragma unroll
        for (int off = 16; off; off >>= 1) p += __shfl_xor_sync(0xffffffffu, p, off);
        float lg = p + bout[0];
        elg = __expf(lg);
        if (l == 0) { out[n + w] = lg; g_elg[w] = elg; }
    }
    if (l == 0) sm[wi] = elg;
    __syncthreads();
    if (threadIdx.x == 0) {
        float s = sm[0];
#pragma unroll
        for (int k = 1; k < 8; k++) s += sm[k];
        atomicAdd(&g_sumexp, s);
    }
}

__global__ void k_weights(float* __restrict__ out, int n) {
    int i = blockIdx.x * blockDim.x + threadIdx.x;
    if (i >= n) return;
    out[i] = g_elg[i] / g_sumexp;
}

// ------------------------- launch (fork/join + agg1/GEMM2 pipeline) -----------
extern "C" void kernel_launch(void* const* d_in, const int* in_sizes, int n_in,
                              void* d_out, int out_size)
{
    const float* x    = (const float*)d_in[0];
    const int*   ei   = (const int*)d_in[1];
    const float* reg  = (const float*)d_in[2];
    const float* ng   = (const float*)d_in[3];
    const float* nb   = (const float*)d_in[4];
    const float* rg   = (const float*)d_in[5];
    const float* rb   = (const float*)d_in[6];
    const float* W1   = (const float*)d_in[7];
    const float* as1  = (const float*)d_in[8];
    const float* ad1  = (const float*)d_in[9];
    const float* b1   = (const float*)d_in[10];
    const float* W2   = (const float*)d_in[11];
    const float* as2  = (const float*)d_in[12];
    const float* ad2  = (const float*)d_in[13];
    const float* b2   = (const float*)d_in[14];
    const float* Wout = (const float*)d_in[15];
    const float* bout = (const float*)d_in[16];
    float* out = (float*)d_out;

    int n = in_sizes[0] / FIN;
    int e = in_sizes[1] / 2;
    int etot = e + n;
    int wb = (n + 7) / 8;
    int nbScan = (n + 1023) / 1024;
    int cntB = (etot + 1023) / 1024;

    cudaStream_t sB;
    cudaStreamCreateWithFlags(&sB, cudaStreamNonBlocking);
    cudaEvent_t evFork, evJoin, evA0, evG0;
    cudaEventCreateWithFlags(&evFork, cudaEventDisableTiming);
    cudaEventCreateWithFlags(&evJoin, cudaEventDisableTiming);
    cudaEventCreateWithFlags(&evA0, cudaEventDisableTiming);
    cudaEventCreateWithFlags(&evG0, cudaEventDisableTiming);

    // fork: CSR chain on stream B
    cudaEventRecord(evFork, 0);
    cudaStreamWaitEvent(sB, evFork, 0);
    k_count<<<cntB, 256, 0, sB>>>(ei, e, etot);
    k_scanA<<<nbScan, 256, 0, sB>>>(n);
    k_scanC<<<nbScan, 256, 0, sB>>>(n, etot);
    k_scatter<<<cntB, 256, 0, sB>>>(ei, e, etot);
    cudaEventRecord(evJoin, sB);

    // compute chain on main stream
    k_phase1a<<<wb + PWB + 1, 256>>>(x, ng, nb, reg, rg, rb, W1, W2, n, wb);
    int nGB = 2 * ((n + 127) / 128);
    k_hgemm1<<<nGB, 256>>>(W1, n);
    k_alpha1<<<wb, 256>>>(as1, ad1, n);

    // join, then pipelined agg1 / GEMM2 halves
    cudaStreamWaitEvent(0, evJoin, 0);

    // half boundary: multiple of 128 rows (GEMM2 tile) and 8 nodes (agg1 block)
    int half = ((n / 2) + 127) / 128 * 128;
    if (half > n) half = n;
    int aggB0 = (half + 7) / 8;
    int aggB1 = (n - half + 7) / 8;
    int g2B0 = (half + 127) / 128;
    int g2B1 = (n - half + 127) / 128;

    k_agg1<<<aggB0, 256>>>(b1, 0, half);
    cudaEventRecord(evA0, 0);

    // GEMM2 on half0 rows runs on stream B while agg1 half1 runs on main
    cudaStreamWaitEvent(sB, evA0, 0);
    if (g2B0 > 0) {
        dim3 gA(1, g2B0);
        k_hgemm2_a2<<<gA, 256, 0, sB>>>(as2, ad2, 0, n);
    }
    cudaEventRecord(evG0, sB);

    if (aggB1 > 0) k_agg1<<<aggB1, 256>>>(b1, half, n);
    if (g2B1 > 0) {
        dim3 gB(1, g2B1);
        k_hgemm2_a2<<<gB, 256>>>(as2, ad2, half, n);
    }
    cudaStreamWaitEvent(0, evG0, 0);

    k_agg2_logits<<<wb, 256>>>(b2, Wout, bout, out, n);
    k_weights<<<(n + 255) / 256, 256>>>(out, n);

    cudaEventDestroy(evFork);
    cudaEventDestroy(evJoin);
    cudaEventDestroy(evA0);
    cudaEventDestroy(evG0);
    cudaStreamDestroy(sB);
}

// round 13
// speedup vs baseline: 1.0245x; 1.0245x over previous
#include <cuda_runtime.h>
#include <cuda_fp16.h>
#include <cstdint>

#define N_MAX 50000
#define E_MAX 1600000
#define ET_MAX (N_MAX + E_MAX)
#define FIN 128
#define F1 256
#define HID 64

#define NEG_SLOPE 0.2f
#define LN_EPS 1e-5f

// ------------------------- scratch (device globals; no allocation) ----------
__device__ __half g_xnh[(size_t)N_MAX * FIN];
__device__ __half g_w1t[(size_t)F1 * FIN];
__device__ __half g_w2t[(size_t)HID * F1];
__device__ __half g_xw1h[(size_t)N_MAX * F1];
__device__ float  g_as1[N_MAX * 4];
__device__ float  g_ad1[N_MAX * 4];
__device__ __half g_h2h[(size_t)N_MAX * F1];
__device__ __half g_xw2h[(size_t)N_MAX * HID];
__device__ float  g_as2[N_MAX];
__device__ float  g_ad2[N_MAX];
__device__ float  g_elg[N_MAX];
__device__ int    g_off[N_MAX + 1];
__device__ int    g_cnt[N_MAX];                  // zero-invariant across calls
__device__ int    g_cur[N_MAX];
__device__ int    g_csrc[ET_MAX];
__device__ float  g_rn[16];
__device__ int    g_bsum[64];
__device__ unsigned g_emax[10];
__device__ float  g_sumexp;

static __device__ __forceinline__ float lrelu(float x) { return x > 0.f ? x : NEG_SLOPE * x; }
static __device__ __forceinline__ float eluf(float x)  { return x > 0.f ? x : (__expf(x) - 1.f); }
static __device__ __forceinline__ unsigned encf(float x) {
    unsigned u = __float_as_uint(x);
    return (u & 0x80000000u) ? ~u : (u | 0x80000000u);
}
static __device__ __forceinline__ float dec_max(unsigned u) {
    return (u & 0x80000000u) ? __uint_as_float(u & 0x7fffffffu) : __uint_as_float(~u);
}
static __device__ __forceinline__ float4 h4f(uint2 u) {
    __half2 a = *(__half2*)&u.x;
    __half2 b = *(__half2*)&u.y;
    float2 fa = __half22float2(a), fb = __half22float2(b);
    return make_float4(fa.x, fa.y, fb.x, fb.y);
}

static __device__ __forceinline__ void ldsm4(unsigned* r, const void* p) {
    unsigned addr = (unsigned)__cvta_generic_to_shared(p);
    asm volatile("ldmatrix.sync.aligned.m8n8.x4.shared.b16 {%0,%1,%2,%3}, [%4];\n"
                 : "=r"(r[0]), "=r"(r[1]), "=r"(r[2]), "=r"(r[3]) : "r"(addr));
}
static __device__ __forceinline__ void mma16816f(float* d, const unsigned* a, const unsigned* b) {
    asm volatile(
        "mma.sync.aligned.m16n8k16.row.col.f32.f16.f16.f32 "
        "{%0,%1,%2,%3}, {%4,%5,%6,%7}, {%8,%9}, {%0,%1,%2,%3};\n"
        : "+f"(d[0]), "+f"(d[1]), "+f"(d[2]), "+f"(d[3])
        : "r"(a[0]), "r"(a[1]), "r"(a[2]), "r"(a[3]), "r"(b[0]), "r"(b[1]));
}

// ===================== stream A: rownorm || prepW || regime/zeros =============
#define PWB 192

__global__ void __launch_bounds__(256) k_phase1a(
    const float* __restrict__ x, const float* __restrict__ gamma,
    const float* __restrict__ beta,
    const float* __restrict__ reg, const float* __restrict__ rg,
    const float* __restrict__ rb,
    const float* __restrict__ W1, const float* __restrict__ W2,
    int n, int wb)
{
    int b = blockIdx.x;
    if (b < wb) {
        int wi = threadIdx.x >> 5;
        int l = threadIdx.x & 31;
        int w = b * 8 + wi;
        if (w >= n) return;
        float4 v = ((const float4*)(x + (size_t)w * FIN))[l];
        float s  = v.x + v.y + v.z + v.w;
        float ss = v.x*v.x + v.y*v.y + v.z*v.z + v.w*v.w;
#pragma unroll
        for (int off = 16; off; off >>= 1) {
            s  += __shfl_xor_sync(0xffffffffu, s, off);
            ss += __shfl_xor_sync(0xffffffffu, ss, off);
        }
        float mu = s * (1.f / FIN);
        float var = ss * (1.f / FIN) - mu * mu;
        float rstd = rsqrtf(var + LN_EPS);
        float4 g = ((const float4*)gamma)[l];
        float4 bb = ((const float4*)beta)[l];
        __half2 p0 = __floats2half2_rn((v.x - mu) * rstd * g.x + bb.x,
                                       (v.y - mu) * rstd * g.y + bb.y);
        __half2 p1 = __floats2half2_rn((v.z - mu) * rstd * g.z + bb.z,
                                       (v.w - mu) * rstd * g.w + bb.w);
        uint2 u; u.x = *(unsigned*)&p0; u.y = *(unsigned*)&p1;
        *(uint2*)(g_xnh + (size_t)w * FIN + 4 * l) = u;
    } else if (b < wb + PWB) {
        int i = (b - wb) * 256 + threadIdx.x;
        if (i < F1 * FIN) {
            int nn = i >> 7, kk = i & 127;
            g_w1t[i] = __float2half(W1[(size_t)kk * F1 + nn]);
        } else {
            int j = i - F1 * FIN;
            if (j < HID * F1) {
                int nn = j >> 8, kk = j & 255;
                g_w2t[j] = __float2half(W2[(size_t)kk * HID + nn]);
            }
        }
    } else {
        int t = threadIdx.x;
        if (t < 32) {
            float v = (t < 16) ? reg[t] : 0.f;
            float s = v, ss = v * v;
#pragma unroll
            for (int off = 16; off; off >>= 1) {
                s  += __shfl_xor_sync(0xffffffffu, s, off);
                ss += __shfl_xor_sync(0xffffffffu, ss, off);
            }
            float mu = s * (1.f / 16.f);
            float var = ss * (1.f / 16.f) - mu * mu;
            float rstd = rsqrtf(var + LN_EPS);
            if (t < 16) g_rn[t] = (v - mu) * rstd * rg[t] + rb[t];
        }
        if (t >= 32 && t < 42) g_emax[t - 32] = 0u;
        if (t == 42) g_sumexp = 0.f;
    }
}

// ===================== stream B: degree count (8 edges/thread) ================
__global__ void __launch_bounds__(256) k_count(const int* __restrict__ ei,
                                               int e, int etot) {
    int base = blockIdx.x * 2048 + threadIdx.x * 8;
    if (base + 7 < e) {
        int4 d0 = *(const int4*)(ei + e + base);
        int4 d1 = *(const int4*)(ei + e + base + 4);
        atomicAdd(&g_cnt[d0.x], 1);
        atomicAdd(&g_cnt[d0.y], 1);
        atomicAdd(&g_cnt[d0.z], 1);
        atomicAdd(&g_cnt[d0.w], 1);
        atomicAdd(&g_cnt[d1.x], 1);
        atomicAdd(&g_cnt[d1.y], 1);
        atomicAdd(&g_cnt[d1.z], 1);
        atomicAdd(&g_cnt[d1.w], 1);
    } else {
#pragma unroll
        for (int j = 0; j < 8; j++) {
            int i = base + j;
            if (i < etot) {
                int d = (i < e) ? ei[e + i] : (i - e);
                atomicAdd(&g_cnt[d], 1);
            }
        }
    }
}

__global__ void __launch_bounds__(256) k_scanA(int n) {
    __shared__ int ssc[256];
    int sb = blockIdx.x, tid = threadIdx.x;
    int base = sb * 1024 + tid * 4;
    int4 v = make_int4(0, 0, 0, 0);
    if (base + 3 < n) {
        v = *(const int4*)(g_cnt + base);
        *(int4*)(g_cnt + base) = make_int4(0, 0, 0, 0);
    } else {
        if (base     < n) { v.x = g_cnt[base];     g_cnt[base] = 0; }
        if (base + 1 < n) { v.y = g_cnt[base + 1]; g_cnt[base + 1] = 0; }
        if (base + 2 < n) { v.z = g_cnt[base + 2]; g_cnt[base + 2] = 0; }
    }
    int s = v.x + v.y + v.z + v.w;
    ssc[tid] = s;
    __syncthreads();
    for (int off = 1; off < 256; off <<= 1) {
        int u = (tid >= off) ? ssc[tid - off] : 0;
        __syncthreads();
        ssc[tid] += u;
        __syncthreads();
    }
    int excl = ssc[tid] - s;
    if (tid == 255) g_bsum[sb] = ssc[255];
    int4 o;
    o.x = excl; o.y = o.x + v.x; o.z = o.y + v.y; o.w = o.z + v.z;
    if (base + 3 < n) *(int4*)(g_off + base) = o;
    else {
        if (base     < n) g_off[base]     = o.x;
        if (base + 1 < n) g_off[base + 1] = o.y;
        if (base + 2 < n) g_off[base + 2] = o.z;
    }
}

__global__ void __launch_bounds__(256) k_scanC(int n, int etot) {
    __shared__ int sbp;
    int cb2 = blockIdx.x;
    int lane = threadIdx.x & 31;
    if (threadIdx.x < 32) {
        int s = 0;
        for (int j = lane; j < cb2; j += 32) s += g_bsum[j];
#pragma unroll
        for (int off = 16; off; off >>= 1) s += __shfl_xor_sync(0xffffffffu, s, off);
        if (lane == 0) sbp = s;
    }
    __syncthreads();
    int bpre = sbp;
    int base = cb2 * 1024 + threadIdx.x * 4;
    if (base + 3 < n) {
        int4 v = *(const int4*)(g_off + base);
        v.x += bpre; v.y += bpre; v.z += bpre; v.w += bpre;
        *(int4*)(g_off + base) = v;
        *(int4*)(g_cur + base) = v;
    } else {
#pragma unroll
        for (int j = 0; j < 4; j++) {
            int i = base + j;
            if (i < n) { int v = g_off[i] + bpre; g_off[i] = v; g_cur[i] = v; }
        }
    }
    if (cb2 == 0 && threadIdx.x == 0) g_off[n] = etot;
}

// ===================== scatter (8 edges/thread, MLP 8) ========================
__global__ void __launch_bounds__(256) k_scatter(const int* __restrict__ ei,
                                                 int e, int etot) {
    int base = blockIdx.x * 2048 + threadIdx.x * 8;
    if (base + 7 < e) {
        int4 s0 = *(const int4*)(ei + base);
        int4 s1 = *(const int4*)(ei + base + 4);
        int4 d0 = *(const int4*)(ei + e + base);
        int4 d1 = *(const int4*)(ei + e + base + 4);
        int p0 = atomicAdd(&g_cur[d0.x], 1);
        int p1 = atomicAdd(&g_cur[d0.y], 1);
        int p2 = atomicAdd(&g_cur[d0.z], 1);
        int p3 = atomicAdd(&g_cur[d0.w], 1);
        int p4 = atomicAdd(&g_cur[d1.x], 1);
        int p5 = atomicAdd(&g_cur[d1.y], 1);
        int p6 = atomicAdd(&g_cur[d1.z], 1);
        int p7 = atomicAdd(&g_cur[d1.w], 1);
        g_csrc[p0] = s0.x; g_csrc[p1] = s0.y;
        g_csrc[p2] = s0.z; g_csrc[p3] = s0.w;
        g_csrc[p4] = s1.x; g_csrc[p5] = s1.y;
        g_csrc[p6] = s1.z; g_csrc[p7] = s1.w;
    } else {
#pragma unroll
        for (int j = 0; j < 8; j++) {
            int i = base + j;
            if (i < etot) {
                int s, d;
                if (i < e) { s = ei[i]; d = ei[e + i]; } else { s = d = i - e; }
                g_csrc[atomicAdd(&g_cur[d], 1)] = s;
            }
        }
    }
}

// ===================== GEMM1 (tensor cores) ===================================
__global__ void __launch_bounds__(256) k_hgemm1(const float* __restrict__ W1, int M)
{
    constexpr int BM = 128, BN = 128, BK = 64, WM = 64, WN = 32, K = FIN;
    constexpr int LDSM = BK + 8;
    __shared__ __align__(16) __half As[BM][LDSM];
    __shared__ __align__(16) __half Bs[BN][LDSM];
    __shared__ float cvs[BN];

    int b = blockIdx.x;
    int tid = threadIdx.x;
    int bx = b & 1, by = b >> 1;
    int wid = tid >> 5, lane = tid & 31;
    constexpr int NWN = BN / WN;
    int wm = wid / NWN, wn = wid % NWN;
    constexpr int MT = WM / 16, NT = WN / 8;
    int rb = by * BM, cb = bx * BN;
    int lr = lane & 7, grp = lane >> 3;

    if (tid < BN) {
        float s = 0.f;
#pragma unroll
        for (int k = 0; k < 16; k++)
            s += g_rn[k] * W1[(size_t)(FIN + k) * F1 + cb + tid];
        cvs[tid] = s;
    }

    float acc[MT][NT][4];
#pragma unroll
    for (int mt = 0; mt < MT; mt++)
#pragma unroll
        for (int nt = 0; nt < NT; nt++)
#pragma unroll
            for (int q = 0; q < 4; q++) acc[mt][nt][q] = 0.f;

    for (int k0 = 0; k0 < K; k0 += BK) {
        constexpr int AV = BM * BK / 8;
#pragma unroll
        for (int s = tid; s < AV; s += 256) {
            int row = s / (BK / 8), seg = s % (BK / 8);
            uint4 v = make_uint4(0u, 0u, 0u, 0u);
            if (rb + row < M) v = *(const uint4*)(g_xnh + (size_t)(rb + row) * K + k0 + seg * 8);
            *(uint4*)&As[row][seg * 8] = v;
        }
        constexpr int BV = BN * BK / 8;
#pragma unroll
        for (int s = tid; s < BV; s += 256) {
            int row = s / (BK / 8), seg = s % (BK / 8);
            *(uint4*)&Bs[row][seg * 8] = *(const uint4*)(g_w1t + (size_t)(cb + row) * K + k0 + seg * 8);
        }
        __syncthreads();
#pragma unroll
        for (int kk = 0; kk < BK; kk += 16) {
            unsigned a[MT][4], bfr[NT][2];
#pragma unroll
            for (int mt = 0; mt < MT; mt++) {
                int r = wm * WM + mt * 16 + (grp & 1) * 8 + lr;
                int c = kk + (grp >> 1) * 8;
                ldsm4(a[mt], &As[r][c]);
            }
#pragma unroll
            for (int np = 0; np < NT; np += 2) {
                int r = wn * WN + np * 8 + (grp >> 1) * 8 + lr;
                int c = kk + (grp & 1) * 8;
                unsigned t[4];
                ldsm4(t, &Bs[r][c]);
                bfr[np][0] = t[0]; bfr[np][1] = t[1];
                bfr[np + 1][0] = t[2]; bfr[np + 1][1] = t[3];
            }
#pragma unroll
            for (int mt = 0; mt < MT; mt++)
#pragma unroll
                for (int nt = 0; nt < NT; nt++)
                    mma16816f(acc[mt][nt], a[mt], bfr[nt]);
        }
        __syncthreads();
    }

    int qr = lane >> 2, qc = (lane & 3) * 2;
#pragma unroll
    for (int mt = 0; mt < MT; mt++)
#pragma unroll
        for (int nt = 0; nt < NT; nt++) {
            int row = rb + wm * WM + mt * 16 + qr;
            int lcol = wn * WN + nt * 8 + qc;
            int col = cb + lcol;
            float2 cv = *(const float2*)&cvs[lcol];
            if (row < M)
                *(__half2*)&g_xw1h[(size_t)row * F1 + col] =
                    __floats2half2_rn(acc[mt][nt][0] + cv.x, acc[mt][nt][1] + cv.y);
            if (row + 8 < M)
                *(__half2*)&g_xw1h[(size_t)(row + 8) * F1 + col] =
                    __floats2half2_rn(acc[mt][nt][2] + cv.x, acc[mt][nt][3] + cv.y);
        }
}

// ===================== alpha1 + per-head maxes ================================
__global__ void __launch_bounds__(256) k_alpha1(const float* __restrict__ asrc,
                                                const float* __restrict__ adst, int n)
{
    __shared__ float smax[8][8];
    int wi = threadIdx.x >> 5;
    int l = threadIdx.x & 31;
    int w = blockIdx.x * 8 + wi;
    const float NEGINF = -3.402823466e38f;
    float ps1 = NEGINF, ps2 = NEGINF, pd1 = NEGINF, pd2 = NEGINF;

    if (w < n) {
        const uint2* xr = (const uint2*)(g_xw1h + (size_t)w * F1);
        float4 x1 = h4f(xr[l]), x2 = h4f(xr[32 + l]);
        float4 s1 = ((const float4*)asrc)[l], s2 = ((const float4*)asrc)[32 + l];
        float4 d1 = ((const float4*)adst)[l], d2 = ((const float4*)adst)[32 + l];
        ps1 = x1.x*s1.x + x1.y*s1.y + x1.z*s1.z + x1.w*s1.w;
        ps2 = x2.x*s2.x + x2.y*s2.y + x2.z*s2.z + x2.w*s2.w;
        pd1 = x1.x*d1.x + x1.y*d1.y + x1.z*d1.z + x1.w*d1.w;
        pd2 = x2.x*d2.x + x2.y*d2.y + x2.z*d2.z + x2.w*d2.w;
#pragma unroll
        for (int off = 8; off; off >>= 1) {
            ps1 += __shfl_xor_sync(0xffffffffu, ps1, off);
            ps2 += __shfl_xor_sync(0xffffffffu, ps2, off);
            pd1 += __shfl_xor_sync(0xffffffffu, pd1, off);
            pd2 += __shfl_xor_sync(0xffffffffu, pd2, off);
        }
        if (l == 0)  { g_as1[w*4+0] = ps1; g_as1[w*4+2] = ps2; g_ad1[w*4+0] = pd1; g_ad1[w*4+2] = pd2; }
        if (l == 16) { g_as1[w*4+1] = ps1; g_as1[w*4+3] = ps2; g_ad1[w*4+1] = pd1; g_ad1[w*4+3] = pd2; }
    }
    if (l == 0)  { smax[0][wi] = ps1; smax[2][wi] = ps2; smax[4][wi] = pd1; smax[6][wi] = pd2; }
    if (l == 16) { smax[1][wi] = ps1; smax[3][wi] = ps2; smax[5][wi] = pd1; smax[7][wi] = pd2; }
    __syncthreads();
    if (threadIdx.x < 8) {
        float m = smax[threadIdx.x][0];
#pragma unroll
        for (int k = 1; k < 8; k++) m = fmaxf(m, smax[threadIdx.x][k]);
        if (m > -3.3e38f) atomicMax(&g_emax[threadIdx.x], encf(m));
    }
}

// -------------- GAT layer-1 aggregation (warp/dst, single pass, unroll 4) ------
__global__ void __launch_bounds__(256) k_agg1(const float* __restrict__ b1, int n) {
    int w = (blockIdx.x * blockDim.x + threadIdx.x) >> 5;
    int l = threadIdx.x & 31;
    if (w >= n) return;
    int head = l >> 3;
    float adh = g_ad1[4 * w + head];
    float Mh = lrelu(dec_max(g_emax[head]) + dec_max(g_emax[4 + head]));
    int start = g_off[w], end = g_off[w + 1];

    float acc[8];
#pragma unroll
    for (int q = 0; q < 8; q++) acc[q] = 0.f;
    float den = 0.f;
    const __half* xw = g_xw1h;

    int i = start;
    for (; i + 4 <= end; i += 4) {
        int s0 = g_csrc[i], s1 = g_csrc[i + 1], s2 = g_csrc[i + 2], s3 = g_csrc[i + 3];
        float e0 = g_as1[4 * s0 + head];
        float e1 = g_as1[4 * s1 + head];
        float e2 = g_as1[4 * s2 + head];
        float e3 = g_as1[4 * s3 + head];
        uint4 x0 = *(const uint4*)(xw + (size_t)s0 * F1 + 8 * l);
        uint4 x1 = *(const uint4*)(xw + (size_t)s1 * F1 + 8 * l);
        uint4 x2 = *(const uint4*)(xw + (size_t)s2 * F1 + 8 * l);
        uint4 x3 = *(const uint4*)(xw + (size_t)s3 * F1 + 8 * l);
        float w0 = __expf(lrelu(e0 + adh) - Mh);
        float w1 = __expf(lrelu(e1 + adh) - Mh);
        float w2 = __expf(lrelu(e2 + adh) - Mh);
        float w3 = __expf(lrelu(e3 + adh) - Mh);
        den += (w0 + w1) + (w2 + w3);
        float4 a0 = h4f(make_uint2(x0.x, x0.y)), a1 = h4f(make_uint2(x0.z, x0.w));
        float4 c0 = h4f(make_uint2(x1.x, x1.y)), c1 = h4f(make_uint2(x1.z, x1.w));
        float4 d0 = h4f(make_uint2(x2.x, x2.y)), d1 = h4f(make_uint2(x2.z, x2.w));
        float4 f0 = h4f(make_uint2(x3.x, x3.y)), f1 = h4f(make_uint2(x3.z, x3.w));
        acc[0] += a0.x * w0 + c0.x * w1 + d0.x * w2 + f0.x * w3;
        acc[1] += a0.y * w0 + c0.y * w1 + d0.y * w2 + f0.y * w3;
        acc[2] += a0.z * w0 + c0.z * w1 + d0.z * w2 + f0.z * w3;
        acc[3] += a0.w * w0 + c0.w * w1 + d0.w * w2 + f0.w * w3;
        acc[4] += a1.x * w0 + c1.x * w1 + d1.x * w2 + f1.x * w3;
        acc[5] += a1.y * w0 + c1.y * w1 + d1.y * w2 + f1.y * w3;
        acc[6] += a1.z * w0 + c1.z * w1 + d1.z * w2 + f1.z * w3;
        acc[7] += a1.w * w0 + c1.w * w1 + d1.w * w2 + f1.w * w3;
    }
    for (; i < end; i++) {
        int s0 = g_csrc[i];
        float e0 = g_as1[4 * s0 + head];
        uint4 x0 = *(const uint4*)(xw + (size_t)s0 * F1 + 8 * l);
        float w0 = __expf(lrelu(e0 + adh) - Mh);
        den += w0;
        float4 a0 = h4f(make_uint2(x0.x, x0.y)), a1 = h4f(make_uint2(x0.z, x0.w));
        acc[0] += a0.x * w0; acc[1] += a0.y * w0;
        acc[2] += a0.z * w0; acc[3] += a0.w * w0;
        acc[4] += a1.x * w0; acc[5] += a1.y * w0;
        acc[6] += a1.z * w0; acc[7] += a1.w * w0;
    }
    float r = 1.f / den;
    const float* bp = b1 + 8 * l;
    float4 bb0 = *(const float4*)bp;
    float4 bb1 = *(const float4*)(bp + 4);
    __half2 q0 = __floats2half2_rn(eluf(acc[0] * r + bb0.x), eluf(acc[1] * r + bb0.y));
    __half2 q1 = __floats2half2_rn(eluf(acc[2] * r + bb0.z), eluf(acc[3] * r + bb0.w));
    __half2 q2 = __floats2half2_rn(eluf(acc[4] * r + bb1.x), eluf(acc[5] * r + bb1.y));
    __half2 q3 = __floats2half2_rn(eluf(acc[6] * r + bb1.z), eluf(acc[7] * r + bb1.w));
    uint4 st;
    st.x = *(unsigned*)&q0; st.y = *(unsigned*)&q1;
    st.z = *(unsigned*)&q2; st.w = *(unsigned*)&q3;
    *(uint4*)(g_h2h + (size_t)w * F1 + 8 * l) = st;
}

// ========== GEMM2 (tensor cores) + fused alpha2 dots + slot maxes =============
__global__ void __launch_bounds__(256) k_hgemm2_a2(const float* __restrict__ asrc,
                                                   const float* __restrict__ adst,
                                                   int M)
{
    constexpr int BM = 128, BN = 64, BK = 64, WM = 32, WN = 32, K = F1;
    constexpr int LDSM = BK + 8;
    __shared__ __align__(16) __half As[BM][LDSM];
    __shared__ __align__(16) __half Bs[BN][LDSM];
    __shared__ float s_as[HID], s_ad[HID];
    __shared__ float s_p[BM], s_q[BM];

    int tid = threadIdx.x;
    int wid = tid >> 5, lane = tid & 31;
    constexpr int NWN = BN / WN;
    int wm = wid / NWN, wn = wid % NWN;
    constexpr int MT = WM / 16, NT = WN / 8;
    int rb = blockIdx.y * BM, cb = 0;
    int lr = lane & 7, grp = lane >> 3;

    if (tid < HID) { s_as[tid] = asrc[tid]; s_ad[tid] = adst[tid]; }
    if (tid < BM)  { s_p[tid] = 0.f; s_q[tid] = 0.f; }

    float acc[MT][NT][4];
#pragma unroll
    for (int mt = 0; mt < MT; mt++)
#pragma unroll
        for (int nt = 0; nt < NT; nt++)
#pragma unroll
            for (int q = 0; q < 4; q++) acc[mt][nt][q] = 0.f;

    for (int k0 = 0; k0 < K; k0 += BK) {
        constexpr int AV = BM * BK / 8;
#pragma unroll
        for (int s = tid; s < AV; s += 256) {
            int row = s / (BK / 8), seg = s % (BK / 8);
            uint4 v = make_uint4(0u, 0u, 0u, 0u);
            if (rb + row < M) v = *(const uint4*)(g_h2h + (size_t)(rb + row) * K + k0 + seg * 8);
            *(uint4*)&As[row][seg * 8] = v;
        }
        constexpr int BV = BN * BK / 8;
#pragma unroll
        for (int s = tid; s < BV; s += 256) {
            int row = s / (BK / 8), seg = s % (BK / 8);
            *(uint4*)&Bs[row][seg * 8] = *(const uint4*)(g_w2t + (size_t)(cb + row) * K + k0 + seg * 8);
        }
        __syncthreads();
#pragma unroll
        for (int kk = 0; kk < BK; kk += 16) {
            unsigned a[MT][4], bfr[NT][2];
#pragma unroll
            for (int mt = 0; mt < MT; mt++) {
                int r = wm * WM + mt * 16 + (grp & 1) * 8 + lr;
                int c = kk + (grp >> 1) * 8;
                ldsm4(a[mt], &As[r][c]);
            }
#pragma unroll
            for (int np = 0; np < NT; np += 2) {
                int r = wn * WN + np * 8 + (grp >> 1) * 8 + lr;
                int c = kk + (grp & 1) * 8;
                unsigned t[4];
                ldsm4(t, &Bs[r][c]);
                bfr[np][0] = t[0]; bfr[np][1] = t[1];
                bfr[np + 1][0] = t[2]; bfr[np + 1][1] = t[3];
            }
#pragma unroll
            for (int mt = 0; mt < MT; mt++)
#pragma unroll
                for (int nt = 0; nt < NT; nt++)
                    mma16816f(acc[mt][nt], a[mt], bfr[nt]);
        }
        __syncthreads();
    }

    int qr = lane >> 2, qc = (lane & 3) * 2;
#pragma unroll
    for (int mt = 0; mt < MT; mt++) {
        float p0 = 0.f, q0v = 0.f, p1 = 0.f, q1v = 0.f;
#pragma unroll
        for (int nt = 0; nt < NT; nt++) {
            int col = wn * WN + nt * 8 + qc;
            float a0 = s_as[col], a1 = s_as[col + 1];
            float d0 = s_ad[col], d1 = s_ad[col + 1];
            p0  += acc[mt][nt][0] * a0 + acc[mt][nt][1] * a1;
            q0v += acc[mt][nt][0] * d0 + acc[mt][nt][1] * d1;
            p1  += acc[mt][nt][2] * a0 + acc[mt][nt][3] * a1;
            q1v += acc[mt][nt][2] * d0 + acc[mt][nt][3] * d1;
            int row = rb + wm * WM + mt * 16 + qr;
            if (row < M)
                *(__half2*)&g_xw2h[(size_t)row * HID + col] =
                    __floats2half2_rn(acc[mt][nt][0], acc[mt][nt][1]);
            if (row + 8 < M)
                *(__half2*)&g_xw2h[(size_t)(row + 8) * HID + col] =
                    __floats2half2_rn(acc[mt][nt][2], acc[mt][nt][3]);
        }
        int lrow = wm * WM + mt * 16 + qr;
        atomicAdd(&s_p[lrow], p0);
        atomicAdd(&s_q[lrow], q0v);
        atomicAdd(&s_p[lrow + 8], p1);
        atomicAdd(&s_q[lrow + 8], q1v);
    }
    __syncthreads();

    if (tid < BM) {
        int grow = rb + tid;
        float pv = s_p[tid], qv = s_q[tid];
        bool ok = (grow < M);
        if (ok) { g_as2[grow] = pv; g_ad2[grow] = qv; }
        float mp = ok ? pv : -3.402823466e38f;
        float mq = ok ? qv : -3.402823466e38f;
#pragma unroll
        for (int off = 16; off; off >>= 1) {
            mp = fmaxf(mp, __shfl_xor_sync(0xffffffffu, mp, off));
            mq = fmaxf(mq, __shfl_xor_sync(0xffffffffu, mq, off));
        }
        if ((tid & 31) == 0 && mp > -3.3e38f) atomicMax(&g_emax[8], encf(mp));
        if ((tid & 31) == 0 && mq > -3.3e38f) atomicMax(&g_emax[9], encf(mq));
    }
}

// ---- GAT layer-2 aggregation + fused logits + exp + sum ----------------------
__global__ void __launch_bounds__(256) k_agg2_logits(const float* __restrict__ b2,
                                                     const float* __restrict__ Wout,
                                                     const float* __restrict__ bout,
                                                     float* __restrict__ out, int n)
{
    __shared__ float sm[8];
    int wi = threadIdx.x >> 5;
    int l = threadIdx.x & 31;
    int w = blockIdx.x * 8 + wi;
    float elg = 0.f;

    if (w < n) {
        int start = g_off[w], end = g_off[w + 1];
        float adv = g_ad2[w];
        float M2 = lrelu(dec_max(g_emax[8]) + dec_max(g_emax[9]));

        float2 acc = make_float2(0.f, 0.f);
        float den = 0.f;
        int i = start;
        for (; i + 2 <= end; i += 2) {
            int s0 = g_csrc[i], s1 = g_csrc[i + 1];
            float e0 = __expf(lrelu(g_as2[s0] + adv) - M2);
            float e1 = __expf(lrelu(g_as2[s1] + adv) - M2);
            float2 x0 = __half22float2(*(const __half2*)&g_xw2h[(size_t)s0 * HID + 2 * l]);
            float2 x1 = __half22float2(*(const __half2*)&g_xw2h[(size_t)s1 * HID + 2 * l]);
            den += e0 + e1;
            acc.x += x0.x * e0 + x1.x * e1;
            acc.y += x0.y * e0 + x1.y * e1;
        }
        if (i < end) {
            int s0 = g_csrc[i];
            float e0 = __expf(lrelu(g_as2[s0] + adv) - M2);
            float2 x0 = __half22float2(*(const __half2*)&g_xw2h[(size_t)s0 * HID + 2 * l]);
            den += e0;
            acc.x += x0.x * e0;
            acc.y += x0.y * e0;
        }
        float r = 1.f / den;
        float2 bb = ((const float2*)b2)[l];
        float ox = eluf(acc.x * r + bb.x);
        float oy = eluf(acc.y * r + bb.y);
        float2 wv = ((const float2*)Wout)[l];
        float p = ox * wv.x + oy * wv.y;
#pragma unroll
        for (int off = 16; off; off >>= 1) p += __shfl_xor_sync(0xffffffffu, p, off);
        float lg = p + bout[0];
        elg = __expf(lg);
        if (l == 0) { out[n + w] = lg; g_elg[w] = elg; }
    }
    if (l == 0) sm[wi] = elg;
    __syncthreads();
    if (threadIdx.x == 0) {
        float s = sm[0];
#pragma unroll
        for (int k = 1; k < 8; k++) s += sm[k];
        atomicAdd(&g_sumexp, s);
    }
}

__global__ void k_weights(float* __restrict__ out, int n) {
    int i = blockIdx.x * blockDim.x + threadIdx.x;
    if (i >= n) return;
    out[i] = g_elg[i] / g_sumexp;
}

// ------------------------- launch (two-stream fork/join) ----------------------
extern "C" void kernel_launch(void* const* d_in, const int* in_sizes, int n_in,
                              void* d_out, int out_size)
{
    const float* x    = (const float*)d_in[0];
    const int*   ei   = (const int*)d_in[1];
    const float* reg  = (const float*)d_in[2];
    const float* ng   = (const float*)d_in[3];
    const float* nb   = (const float*)d_in[4];
    const float* rg   = (const float*)d_in[5];
    const float* rb   = (const float*)d_in[6];
    const float* W1   = (const float*)d_in[7];
    const float* as1  = (const float*)d_in[8];
    const float* ad1  = (const float*)d_in[9];
    const float* b1   = (const float*)d_in[10];
    const float* W2   = (const float*)d_in[11];
    const float* as2  = (const float*)d_in[12];
    const float* ad2  = (const float*)d_in[13];
    const float* b2   = (const float*)d_in[14];
    const float* Wout = (const float*)d_in[15];
    const float* bout = (const float*)d_in[16];
    float* out = (float*)d_out;

    int n = in_sizes[0] / FIN;
    int e = in_sizes[1] / 2;
    int etot = e + n;
    int wb = (n + 7) / 8;
    int nbScan = (n + 1023) / 1024;
    int edgeB = (etot + 2047) / 2048;

    cudaStream_t sB;
    cudaStreamCreateWithFlags(&sB, cudaStreamNonBlocking);
    cudaEvent_t evFork, evJoin;
    cudaEventCreateWithFlags(&evFork, cudaEventDisableTiming);
    cudaEventCreateWithFlags(&evJoin, cudaEventDisableTiming);

    // fork: CSR chain on stream B (independent of compute chain until agg1)
    cudaEventRecord(evFork, 0);
    cudaStreamWaitEvent(sB, evFork, 0);
    k_count<<<edgeB, 256, 0, sB>>>(ei, e, etot);
    k_scanA<<<nbScan, 256, 0, sB>>>(n);
    k_scanC<<<nbScan, 256, 0, sB>>>(n, etot);
    k_scatter<<<edgeB, 256, 0, sB>>>(ei, e, etot);
    cudaEventRecord(evJoin, sB);

    // compute chain on main stream
    k_phase1a<<<wb + PWB + 1, 256>>>(x, ng, nb, reg, rg, rb, W1, W2, n, wb);
    int nGB = 2 * ((n + 127) / 128);
    k_hgemm1<<<nGB, 256>>>(W1, n);
    k_alpha1<<<wb, 256>>>(as1, ad1, n);

    // join: agg1 needs CSR + alpha1
    cudaStreamWaitEvent(0, evJoin, 0);
    k_agg1<<<wb, 256>>>(b1, n);

    dim3 g2(1, (n + 127) / 128);
    k_hgemm2_a2<<<g2, 256>>>(as2, ad2, n);
    k_agg2_logits<<<wb, 256>>>(b2, Wout, bout, out, n);
    k_weights<<<(n + 255) / 256, 256>>>(out, n);

    cudaEventDestroy(evFork);
    cudaEventDestroy(evJoin);
    cudaStreamDestroy(sB);
}

// round 14
// speedup vs baseline: 1.0321x; 1.0074x over previous
#include <cuda_runtime.h>
#include <cuda_fp16.h>
#include <cstdint>

#define N_MAX 50000
#define E_MAX 1600000
#define ET_MAX (N_MAX + E_MAX)
#define FIN 128
#define F1 256
#define HID 64

#define NEG_SLOPE 0.2f
#define LN_EPS 1e-5f

// ------------------------- scratch (device globals; no allocation) ----------
__device__ __half g_xnh[(size_t)N_MAX * FIN];
__device__ __half g_w1t[(size_t)F1 * FIN];
__device__ __half g_w2t[(size_t)HID * F1];
__device__ __half g_xw1h[(size_t)N_MAX * F1];
__device__ float  g_as1[N_MAX * 4];
__device__ float  g_ad1[N_MAX * 4];
__device__ __half g_h2h[(size_t)N_MAX * F1];
__device__ __half g_xw2h[(size_t)N_MAX * HID];
__device__ float  g_as2[N_MAX];
__device__ float  g_ad2[N_MAX];
__device__ float  g_elg[N_MAX];
__device__ int    g_off[N_MAX + 1];
__device__ int    g_cnt[N_MAX];                  // zero-invariant across calls
__device__ int    g_cur[N_MAX];
__device__ int    g_csrc[ET_MAX];
__device__ float  g_rn[16];
__device__ int    g_bsum[64];
__device__ unsigned g_emax[10];
__device__ float  g_sumexp;

static __device__ __forceinline__ float lrelu(float x) { return x > 0.f ? x : NEG_SLOPE * x; }
static __device__ __forceinline__ float eluf(float x)  { return x > 0.f ? x : (__expf(x) - 1.f); }
static __device__ __forceinline__ unsigned encf(float x) {
    unsigned u = __float_as_uint(x);
    return (u & 0x80000000u) ? ~u : (u | 0x80000000u);
}
static __device__ __forceinline__ float dec_max(unsigned u) {
    return (u & 0x80000000u) ? __uint_as_float(u & 0x7fffffffu) : __uint_as_float(~u);
}
static __device__ __forceinline__ float4 h4f(uint2 u) {
    __half2 a = *(__half2*)&u.x;
    __half2 b = *(__half2*)&u.y;
    float2 fa = __half22float2(a), fb = __half22float2(b);
    return make_float4(fa.x, fa.y, fb.x, fb.y);
}

static __device__ __forceinline__ void ldsm4(unsigned* r, const void* p) {
    unsigned addr = (unsigned)__cvta_generic_to_shared(p);
    asm volatile("ldmatrix.sync.aligned.m8n8.x4.shared.b16 {%0,%1,%2,%3}, [%4];\n"
                 : "=r"(r[0]), "=r"(r[1]), "=r"(r[2]), "=r"(r[3]) : "r"(addr));
}
static __device__ __forceinline__ void mma16816f(float* d, const unsigned* a, const unsigned* b) {
    asm volatile(
        "mma.sync.aligned.m16n8k16.row.col.f32.f16.f16.f32 "
        "{%0,%1,%2,%3}, {%4,%5,%6,%7}, {%8,%9}, {%0,%1,%2,%3};\n"
        : "+f"(d[0]), "+f"(d[1]), "+f"(d[2]), "+f"(d[3])
        : "r"(a[0]), "r"(a[1]), "r"(a[2]), "r"(a[3]), "r"(b[0]), "r"(b[1]));
}

// ===================== stream A: rownorm || prepW || regime/zeros =============
#define PWB 192

__global__ void __launch_bounds__(256) k_phase1a(
    const float* __restrict__ x, const float* __restrict__ gamma,
    const float* __restrict__ beta,
    const float* __restrict__ reg, const float* __restrict__ rg,
    const float* __restrict__ rb,
    const float* __restrict__ W1, const float* __restrict__ W2,
    int n, int wb)
{
    int b = blockIdx.x;
    if (b < wb) {
        int wi = threadIdx.x >> 5;
        int l = threadIdx.x & 31;
        int w = b * 8 + wi;
        if (w >= n) return;
        float4 v = ((const float4*)(x + (size_t)w * FIN))[l];
        float s  = v.x + v.y + v.z + v.w;
        float ss = v.x*v.x + v.y*v.y + v.z*v.z + v.w*v.w;
#pragma unroll
        for (int off = 16; off; off >>= 1) {
            s  += __shfl_xor_sync(0xffffffffu, s, off);
            ss += __shfl_xor_sync(0xffffffffu, ss, off);
        }
        float mu = s * (1.f / FIN);
        float var = ss * (1.f / FIN) - mu * mu;
        float rstd = rsqrtf(var + LN_EPS);
        float4 g = ((const float4*)gamma)[l];
        float4 bb = ((const float4*)beta)[l];
        __half2 p0 = __floats2half2_rn((v.x - mu) * rstd * g.x + bb.x,
                                       (v.y - mu) * rstd * g.y + bb.y);
        __half2 p1 = __floats2half2_rn((v.z - mu) * rstd * g.z + bb.z,
                                       (v.w - mu) * rstd * g.w + bb.w);
        uint2 u; u.x = *(unsigned*)&p0; u.y = *(unsigned*)&p1;
        *(uint2*)(g_xnh + (size_t)w * FIN + 4 * l) = u;
    } else if (b < wb + PWB) {
        int i = (b - wb) * 256 + threadIdx.x;
        if (i < F1 * FIN) {
            int nn = i >> 7, kk = i & 127;
            g_w1t[i] = __float2half(W1[(size_t)kk * F1 + nn]);
        } else {
            int j = i - F1 * FIN;
            if (j < HID * F1) {
                int nn = j >> 8, kk = j & 255;
                g_w2t[j] = __float2half(W2[(size_t)kk * HID + nn]);
            }
        }
    } else {
        int t = threadIdx.x;
        if (t < 32) {
            float v = (t < 16) ? reg[t] : 0.f;
            float s = v, ss = v * v;
#pragma unroll
            for (int off = 16; off; off >>= 1) {
                s  += __shfl_xor_sync(0xffffffffu, s, off);
                ss += __shfl_xor_sync(0xffffffffu, ss, off);
            }
            float mu = s * (1.f / 16.f);
            float var = ss * (1.f / 16.f) - mu * mu;
            float rstd = rsqrtf(var + LN_EPS);
            if (t < 16) g_rn[t] = (v - mu) * rstd * rg[t] + rb[t];
        }
        if (t >= 32 && t < 42) g_emax[t - 32] = 0u;
        if (t == 42) g_sumexp = 0.f;
    }
}

// ===================== stream B: degree count (4 edges/thread) ================
__global__ void __launch_bounds__(256) k_count(const int* __restrict__ ei,
                                               int e, int etot) {
    int base = blockIdx.x * 1024 + threadIdx.x * 4;
    if (base + 3 < e) {
        int4 dd = *(const int4*)(ei + e + base);
        atomicAdd(&g_cnt[dd.x], 1);
        atomicAdd(&g_cnt[dd.y], 1);
        atomicAdd(&g_cnt[dd.z], 1);
        atomicAdd(&g_cnt[dd.w], 1);
    } else {
#pragma unroll
        for (int j = 0; j < 4; j++) {
            int i = base + j;
            if (i < etot) {
                int d = (i < e) ? ei[e + i] : (i - e);
                atomicAdd(&g_cnt[d], 1);
            }
        }
    }
}

__global__ void __launch_bounds__(256) k_scanA(int n) {
    __shared__ int ssc[256];
    int sb = blockIdx.x, tid = threadIdx.x;
    int base = sb * 1024 + tid * 4;
    int4 v = make_int4(0, 0, 0, 0);
    if (base + 3 < n) {
        v = *(const int4*)(g_cnt + base);
        *(int4*)(g_cnt + base) = make_int4(0, 0, 0, 0);
    } else {
        if (base     < n) { v.x = g_cnt[base];     g_cnt[base] = 0; }
        if (base + 1 < n) { v.y = g_cnt[base + 1]; g_cnt[base + 1] = 0; }
        if (base + 2 < n) { v.z = g_cnt[base + 2]; g_cnt[base + 2] = 0; }
    }
    int s = v.x + v.y + v.z + v.w;
    ssc[tid] = s;
    __syncthreads();
    for (int off = 1; off < 256; off <<= 1) {
        int u = (tid >= off) ? ssc[tid - off] : 0;
        __syncthreads();
        ssc[tid] += u;
        __syncthreads();
    }
    int excl = ssc[tid] - s;
    if (tid == 255) g_bsum[sb] = ssc[255];
    int4 o;
    o.x = excl; o.y = o.x + v.x; o.z = o.y + v.y; o.w = o.z + v.z;
    if (base + 3 < n) *(int4*)(g_off + base) = o;
    else {
        if (base     < n) g_off[base]     = o.x;
        if (base + 1 < n) g_off[base + 1] = o.y;
        if (base + 2 < n) g_off[base + 2] = o.z;
    }
}

__global__ void __launch_bounds__(256) k_scanC(int n, int etot) {
    __shared__ int sbp;
    int cb2 = blockIdx.x;
    int lane = threadIdx.x & 31;
    if (threadIdx.x < 32) {
        int s = 0;
        for (int j = lane; j < cb2; j += 32) s += g_bsum[j];
#pragma unroll
        for (int off = 16; off; off >>= 1) s += __shfl_xor_sync(0xffffffffu, s, off);
        if (lane == 0) sbp = s;
    }
    __syncthreads();
    int bpre = sbp;
    int base = cb2 * 1024 + threadIdx.x * 4;
    if (base + 3 < n) {
        int4 v = *(const int4*)(g_off + base);
        v.x += bpre; v.y += bpre; v.z += bpre; v.w += bpre;
        *(int4*)(g_off + base) = v;
        *(int4*)(g_cur + base) = v;
    } else {
#pragma unroll
        for (int j = 0; j < 4; j++) {
            int i = base + j;
            if (i < n) { int v = g_off[i] + bpre; g_off[i] = v; g_cur[i] = v; }
        }
    }
    if (cb2 == 0 && threadIdx.x == 0) g_off[n] = etot;
}

// ===================== scatter (4 edges/thread) ===============================
__global__ void __launch_bounds__(256) k_scatter(const int* __restrict__ ei,
                                                 int e, int etot) {
    int base = blockIdx.x * 1024 + threadIdx.x * 4;
    if (base + 3 < e) {
        int4 ssv = *(const int4*)(ei + base);
        int4 ddv = *(const int4*)(ei + e + base);
        g_csrc[atomicAdd(&g_cur[ddv.x], 1)] = ssv.x;
        g_csrc[atomicAdd(&g_cur[ddv.y], 1)] = ssv.y;
        g_csrc[atomicAdd(&g_cur[ddv.z], 1)] = ssv.z;
        g_csrc[atomicAdd(&g_cur[ddv.w], 1)] = ssv.w;
    } else {
#pragma unroll
        for (int j = 0; j < 4; j++) {
            int i = base + j;
            if (i < etot) {
                int s, d;
                if (i < e) { s = ei[i]; d = ei[e + i]; } else { s = d = i - e; }
                g_csrc[atomicAdd(&g_cur[d], 1)] = s;
            }
        }
    }
}

// ===================== GEMM1 (tensor cores) ===================================
__global__ void __launch_bounds__(256) k_hgemm1(const float* __restrict__ W1, int M)
{
    constexpr int BM = 128, BN = 128, BK = 64, WM = 64, WN = 32, K = FIN;
    constexpr int LDSM = BK + 8;
    __shared__ __align__(16) __half As[BM][LDSM];
    __shared__ __align__(16) __half Bs[BN][LDSM];
    __shared__ float cvs[BN];

    int b = blockIdx.x;
    int tid = threadIdx.x;
    int bx = b & 1, by = b >> 1;
    int wid = tid >> 5, lane = tid & 31;
    constexpr int NWN = BN / WN;
    int wm = wid / NWN, wn = wid % NWN;
    constexpr int MT = WM / 16, NT = WN / 8;
    int rb = by * BM, cb = bx * BN;
    int lr = lane & 7, grp = lane >> 3;

    if (tid < BN) {
        float s = 0.f;
#pragma unroll
        for (int k = 0; k < 16; k++)
            s += g_rn[k] * W1[(size_t)(FIN + k) * F1 + cb + tid];
        cvs[tid] = s;
    }

    float acc[MT][NT][4];
#pragma unroll
    for (int mt = 0; mt < MT; mt++)
#pragma unroll
        for (int nt = 0; nt < NT; nt++)
#pragma unroll
            for (int q = 0; q < 4; q++) acc[mt][nt][q] = 0.f;

    for (int k0 = 0; k0 < K; k0 += BK) {
        constexpr int AV = BM * BK / 8;
#pragma unroll
        for (int s = tid; s < AV; s += 256) {
            int row = s / (BK / 8), seg = s % (BK / 8);
            uint4 v = make_uint4(0u, 0u, 0u, 0u);
            if (rb + row < M) v = *(const uint4*)(g_xnh + (size_t)(rb + row) * K + k0 + seg * 8);
            *(uint4*)&As[row][seg * 8] = v;
        }
        constexpr int BV = BN * BK / 8;
#pragma unroll
        for (int s = tid; s < BV; s += 256) {
            int row = s / (BK / 8), seg = s % (BK / 8);
            *(uint4*)&Bs[row][seg * 8] = *(const uint4*)(g_w1t + (size_t)(cb + row) * K + k0 + seg * 8);
        }
        __syncthreads();
#pragma unroll
        for (int kk = 0; kk < BK; kk += 16) {
            unsigned a[MT][4], bfr[NT][2];
#pragma unroll
            for (int mt = 0; mt < MT; mt++) {
                int r = wm * WM + mt * 16 + (grp & 1) * 8 + lr;
                int c = kk + (grp >> 1) * 8;
                ldsm4(a[mt], &As[r][c]);
            }
#pragma unroll
            for (int np = 0; np < NT; np += 2) {
                int r = wn * WN + np * 8 + (grp >> 1) * 8 + lr;
                int c = kk + (grp & 1) * 8;
                unsigned t[4];
                ldsm4(t, &Bs[r][c]);
                bfr[np][0] = t[0]; bfr[np][1] = t[1];
                bfr[np + 1][0] = t[2]; bfr[np + 1][1] = t[3];
            }
#pragma unroll
            for (int mt = 0; mt < MT; mt++)
#pragma unroll
                for (int nt = 0; nt < NT; nt++)
                    mma16816f(acc[mt][nt], a[mt], bfr[nt]);
        }
        __syncthreads();
    }

    int qr = lane >> 2, qc = (lane & 3) * 2;
#pragma unroll
    for (int mt = 0; mt < MT; mt++)
#pragma unroll
        for (int nt = 0; nt < NT; nt++) {
            int row = rb + wm * WM + mt * 16 + qr;
            int lcol = wn * WN + nt * 8 + qc;
            int col = cb + lcol;
            float2 cv = *(const float2*)&cvs[lcol];
            if (row < M)
                *(__half2*)&g_xw1h[(size_t)row * F1 + col] =
                    __floats2half2_rn(acc[mt][nt][0] + cv.x, acc[mt][nt][1] + cv.y);
            if (row + 8 < M)
                *(__half2*)&g_xw1h[(size_t)(row + 8) * F1 + col] =
                    __floats2half2_rn(acc[mt][nt][2] + cv.x, acc[mt][nt][3] + cv.y);
        }
}

// ===================== alpha1 + per-head maxes ================================
__global__ void __launch_bounds__(256) k_alpha1(const float* __restrict__ asrc,
                                                const float* __restrict__ adst, int n)
{
    __shared__ float smax[8][8];
    int wi = threadIdx.x >> 5;
    int l = threadIdx.x & 31;
    int w = blockIdx.x * 8 + wi;
    const float NEGINF = -3.402823466e38f;
    float ps1 = NEGINF, ps2 = NEGINF, pd1 = NEGINF, pd2 = NEGINF;

    if (w < n) {
        const uint2* xr = (const uint2*)(g_xw1h + (size_t)w * F1);
        float4 x1 = h4f(xr[l]), x2 = h4f(xr[32 + l]);
        float4 s1 = ((const float4*)asrc)[l], s2 = ((const float4*)asrc)[32 + l];
        float4 d1 = ((const float4*)adst)[l], d2 = ((const float4*)adst)[32 + l];
        ps1 = x1.x*s1.x + x1.y*s1.y + x1.z*s1.z + x1.w*s1.w;
        ps2 = x2.x*s2.x + x2.y*s2.y + x2.z*s2.z + x2.w*s2.w;
        pd1 = x1.x*d1.x + x1.y*d1.y + x1.z*d1.z + x1.w*d1.w;
        pd2 = x2.x*d2.x + x2.y*d2.y + x2.z*d2.z + x2.w*d2.w;
#pragma unroll
        for (int off = 8; off; off >>= 1) {
            ps1 += __shfl_xor_sync(0xffffffffu, ps1, off);
            ps2 += __shfl_xor_sync(0xffffffffu, ps2, off);
            pd1 += __shfl_xor_sync(0xffffffffu, pd1, off);
            pd2 += __shfl_xor_sync(0xffffffffu, pd2, off);
        }
        if (l == 0)  { g_as1[w*4+0] = ps1; g_as1[w*4+2] = ps2; g_ad1[w*4+0] = pd1; g_ad1[w*4+2] = pd2; }
        if (l == 16) { g_as1[w*4+1] = ps1; g_as1[w*4+3] = ps2; g_ad1[w*4+1] = pd1; g_ad1[w*4+3] = pd2; }
    }
    if (l == 0)  { smax[0][wi] = ps1; smax[2][wi] = ps2; smax[4][wi] = pd1; smax[6][wi] = pd2; }
    if (l == 16) { smax[1][wi] = ps1; smax[3][wi] = ps2; smax[5][wi] = pd1; smax[7][wi] = pd2; }
    __syncthreads();
    if (threadIdx.x < 8) {
        float m = smax[threadIdx.x][0];
#pragma unroll
        for (int k = 1; k < 8; k++) m = fmaxf(m, smax[threadIdx.x][k]);
        if (m > -3.3e38f) atomicMax(&g_emax[threadIdx.x], encf(m));
    }
}

// -------------- GAT layer-1 aggregation (warp/dst, single pass, unroll 4) ------
__global__ void __launch_bounds__(256) k_agg1(const float* __restrict__ b1, int n) {
    int w = (blockIdx.x * blockDim.x + threadIdx.x) >> 5;
    int l = threadIdx.x & 31;
    if (w >= n) return;
    int head = l >> 3;
    float adh = g_ad1[4 * w + head];
    float Mh = lrelu(dec_max(g_emax[head]) + dec_max(g_emax[4 + head]));
    int start = g_off[w], end = g_off[w + 1];

    float acc[8];
#pragma unroll
    for (int q = 0; q < 8; q++) acc[q] = 0.f;
    float den = 0.f;
    const __half* xw = g_xw1h;

    int i = start;
    for (; i + 4 <= end; i += 4) {
        int s0 = g_csrc[i], s1 = g_csrc[i + 1], s2 = g_csrc[i + 2], s3 = g_csrc[i + 3];
        float e0 = g_as1[4 * s0 + head];
        float e1 = g_as1[4 * s1 + head];
        float e2 = g_as1[4 * s2 + head];
        float e3 = g_as1[4 * s3 + head];
        uint4 x0 = *(const uint4*)(xw + (size_t)s0 * F1 + 8 * l);
        uint4 x1 = *(const uint4*)(xw + (size_t)s1 * F1 + 8 * l);
        uint4 x2 = *(const uint4*)(xw + (size_t)s2 * F1 + 8 * l);
        uint4 x3 = *(const uint4*)(xw + (size_t)s3 * F1 + 8 * l);
        float w0 = __expf(lrelu(e0 + adh) - Mh);
        float w1 = __expf(lrelu(e1 + adh) - Mh);
        float w2 = __expf(lrelu(e2 + adh) - Mh);
        float w3 = __expf(lrelu(e3 + adh) - Mh);
        den += (w0 + w1) + (w2 + w3);
        float4 a0 = h4f(make_uint2(x0.x, x0.y)), a1 = h4f(make_uint2(x0.z, x0.w));
        float4 c0 = h4f(make_uint2(x1.x, x1.y)), c1 = h4f(make_uint2(x1.z, x1.w));
        float4 d0 = h4f(make_uint2(x2.x, x2.y)), d1 = h4f(make_uint2(x2.z, x2.w));
        float4 f0 = h4f(make_uint2(x3.x, x3.y)), f1 = h4f(make_uint2(x3.z, x3.w));
        acc[0] += a0.x * w0 + c0.x * w1 + d0.x * w2 + f0.x * w3;
        acc[1] += a0.y * w0 + c0.y * w1 + d0.y * w2 + f0.y * w3;
        acc[2] += a0.z * w0 + c0.z * w1 + d0.z * w2 + f0.z * w3;
        acc[3] += a0.w * w0 + c0.w * w1 + d0.w * w2 + f0.w * w3;
        acc[4] += a1.x * w0 + c1.x * w1 + d1.x * w2 + f1.x * w3;
        acc[5] += a1.y * w0 + c1.y * w1 + d1.y * w2 + f1.y * w3;
        acc[6] += a1.z * w0 + c1.z * w1 + d1.z * w2 + f1.z * w3;
        acc[7] += a1.w * w0 + c1.w * w1 + d1.w * w2 + f1.w * w3;
    }
    for (; i < end; i++) {
        int s0 = g_csrc[i];
        float e0 = g_as1[4 * s0 + head];
        uint4 x0 = *(const uint4*)(xw + (size_t)s0 * F1 + 8 * l);
        float w0 = __expf(lrelu(e0 + adh) - Mh);
        den += w0;
        float4 a0 = h4f(make_uint2(x0.x, x0.y)), a1 = h4f(make_uint2(x0.z, x0.w));
        acc[0] += a0.x * w0; acc[1] += a0.y * w0;
        acc[2] += a0.z * w0; acc[3] += a0.w * w0;
        acc[4] += a1.x * w0; acc[5] += a1.y * w0;
        acc[6] += a1.z * w0; acc[7] += a1.w * w0;
    }
    float r = 1.f / den;
    const float* bp = b1 + 8 * l;
    float4 bb0 = *(const float4*)bp;
    float4 bb1 = *(const float4*)(bp + 4);
    __half2 q0 = __floats2half2_rn(eluf(acc[0] * r + bb0.x), eluf(acc[1] * r + bb0.y));
    __half2 q1 = __floats2half2_rn(eluf(acc[2] * r + bb0.z), eluf(acc[3] * r + bb0.w));
    __half2 q2 = __floats2half2_rn(eluf(acc[4] * r + bb1.x), eluf(acc[5] * r + bb1.y));
    __half2 q3 = __floats2half2_rn(eluf(acc[6] * r + bb1.z), eluf(acc[7] * r + bb1.w));
    uint4 st;
    st.x = *(unsigned*)&q0; st.y = *(unsigned*)&q1;
    st.z = *(unsigned*)&q2; st.w = *(unsigned*)&q3;
    *(uint4*)(g_h2h + (size_t)w * F1 + 8 * l) = st;
}

// ========== GEMM2 (tensor cores) + fused alpha2 dots + slot maxes =============
__global__ void __launch_bounds__(256) k_hgemm2_a2(const float* __restrict__ asrc,
                                                   const float* __restrict__ adst,
                                                   int M)
{
    constexpr int BM = 128, BN = 64, BK = 64, WM = 32, WN = 32, K = F1;
    constexpr int LDSM = BK + 8;
    __shared__ __align__(16) __half As[BM][LDSM];
    __shared__ __align__(16) __half Bs[BN][LDSM];
    __shared__ float s_as[HID], s_ad[HID];
    __shared__ float s_p[BM], s_q[BM];

    int tid = threadIdx.x;
    int wid = tid >> 5, lane = tid & 31;
    constexpr int NWN = BN / WN;
    int wm = wid / NWN, wn = wid % NWN;
    constexpr int MT = WM / 16, NT = WN / 8;
    int rb = blockIdx.y * BM, cb = 0;
    int lr = lane & 7, grp = lane >> 3;

    if (tid < HID) { s_as[tid] = asrc[tid]; s_ad[tid] = adst[tid]; }
    if (tid < BM)  { s_p[tid] = 0.f; s_q[tid] = 0.f; }

    float acc[MT][NT][4];
#pragma unroll
    for (int mt = 0; mt < MT; mt++)
#pragma unroll
        for (int nt = 0; nt < NT; nt++)
#pragma unroll
            for (int q = 0; q < 4; q++) acc[mt][nt][q] = 0.f;

    for (int k0 = 0; k0 < K; k0 += BK) {
        constexpr int AV = BM * BK / 8;
#pragma unroll
        for (int s = tid; s < AV; s += 256) {
            int row = s / (BK / 8), seg = s % (BK / 8);
            uint4 v = make_uint4(0u, 0u, 0u, 0u);
            if (rb + row < M) v = *(const uint4*)(g_h2h + (size_t)(rb + row) * K + k0 + seg * 8);
            *(uint4*)&As[row][seg * 8] = v;
        }
        constexpr int BV = BN * BK / 8;
#pragma unroll
        for (int s = tid; s < BV; s += 256) {
            int row = s / (BK / 8), seg = s % (BK / 8);
            *(uint4*)&Bs[row][seg * 8] = *(const uint4*)(g_w2t + (size_t)(cb + row) * K + k0 + seg * 8);
        }
        __syncthreads();
#pragma unroll
        for (int kk = 0; kk < BK; kk += 16) {
            unsigned a[MT][4], bfr[NT][2];
#pragma unroll
            for (int mt = 0; mt < MT; mt++) {
                int r = wm * WM + mt * 16 + (grp & 1) * 8 + lr;
                int c = kk + (grp >> 1) * 8;
                ldsm4(a[mt], &As[r][c]);
            }
#pragma unroll
            for (int np = 0; np < NT; np += 2) {
                int r = wn * WN + np * 8 + (grp >> 1) * 8 + lr;
                int c = kk + (grp & 1) * 8;
                unsigned t[4];
                ldsm4(t, &Bs[r][c]);
                bfr[np][0] = t[0]; bfr[np][1] = t[1];
                bfr[np + 1][0] = t[2]; bfr[np + 1][1] = t[3];
            }
#pragma unroll
            for (int mt = 0; mt < MT; mt++)
#pragma unroll
                for (int nt = 0; nt < NT; nt++)
                    mma16816f(acc[mt][nt], a[mt], bfr[nt]);
        }
        __syncthreads();
    }

    int qr = lane >> 2, qc = (lane & 3) * 2;
#pragma unroll
    for (int mt = 0; mt < MT; mt++) {
        float p0 = 0.f, q0v = 0.f, p1 = 0.f, q1v = 0.f;
#pragma unroll
        for (int nt = 0; nt < NT; nt++) {
            int col = wn * WN + nt * 8 + qc;
            float a0 = s_as[col], a1 = s_as[col + 1];
            float d0 = s_ad[col], d1 = s_ad[col + 1];
            p0  += acc[mt][nt][0] * a0 + acc[mt][nt][1] * a1;
            q0v += acc[mt][nt][0] * d0 + acc[mt][nt][1] * d1;
            p1  += acc[mt][nt][2] * a0 + acc[mt][nt][3] * a1;
            q1v += acc[mt][nt][2] * d0 + acc[mt][nt][3] * d1;
            int row = rb + wm * WM + mt * 16 + qr;
            if (row < M)
                *(__half2*)&g_xw2h[(size_t)row * HID + col] =
                    __floats2half2_rn(acc[mt][nt][0], acc[mt][nt][1]);
            if (row + 8 < M)
                *(__half2*)&g_xw2h[(size_t)(row + 8) * HID + col] =
                    __floats2half2_rn(acc[mt][nt][2], acc[mt][nt][3]);
        }
        int lrow = wm * WM + mt * 16 + qr;
        atomicAdd(&s_p[lrow], p0);
        atomicAdd(&s_q[lrow], q0v);
        atomicAdd(&s_p[lrow + 8], p1);
        atomicAdd(&s_q[lrow + 8], q1v);
    }
    __syncthreads();

    if (tid < BM) {
        int grow = rb + tid;
        float pv = s_p[tid], qv = s_q[tid];
        bool ok = (grow < M);
        if (ok) { g_as2[grow] = pv; g_ad2[grow] = qv; }
        float mp = ok ? pv : -3.402823466e38f;
        float mq = ok ? qv : -3.402823466e38f;
#pragma unroll
        for (int off = 16; off; off >>= 1) {
            mp = fmaxf(mp, __shfl_xor_sync(0xffffffffu, mp, off));
            mq = fmaxf(mq, __shfl_xor_sync(0xffffffffu, mq, off));
        }
        if ((tid & 31) == 0 && mp > -3.3e38f) atomicMax(&g_emax[8], encf(mp));
        if ((tid & 31) == 0 && mq > -3.3e38f) atomicMax(&g_emax[9], encf(mq));
    }
}

// ---- GAT layer-2 aggregation + fused logits + exp + sum (unroll 4) -----------
__global__ void __launch_bounds__(256) k_agg2_logits(const float* __restrict__ b2,
                                                     const float* __restrict__ Wout,
                                                     const float* __restrict__ bout,
                                                     float* __restrict__ out, int n)
{
    __shared__ float sm[8];
    int wi = threadIdx.x >> 5;
    int l = threadIdx.x & 31;
    int w = blockIdx.x * 8 + wi;
    float elg = 0.f;

    if (w < n) {
        int start = g_off[w], end = g_off[w + 1];
        float adv = g_ad2[w];
        float M2 = lrelu(dec_max(g_emax[8]) + dec_max(g_emax[9]));

        float2 acc = make_float2(0.f, 0.f);
        float den = 0.f;
        int i = start;
        for (; i + 4 <= end; i += 4) {
            int s0 = g_csrc[i], s1 = g_csrc[i + 1], s2 = g_csrc[i + 2], s3 = g_csrc[i + 3];
            float e0 = __expf(lrelu(g_as2[s0] + adv) - M2);
            float e1 = __expf(lrelu(g_as2[s1] + adv) - M2);
            float e2 = __expf(lrelu(g_as2[s2] + adv) - M2);
            float e3 = __expf(lrelu(g_as2[s3] + adv) - M2);
            float2 x0 = __half22float2(*(const __half2*)&g_xw2h[(size_t)s0 * HID + 2 * l]);
            float2 x1 = __half22float2(*(const __half2*)&g_xw2h[(size_t)s1 * HID + 2 * l]);
            float2 x2 = __half22float2(*(const __half2*)&g_xw2h[(size_t)s2 * HID + 2 * l]);
            float2 x3 = __half22float2(*(const __half2*)&g_xw2h[(size_t)s3 * HID + 2 * l]);
            den += (e0 + e1) + (e2 + e3);
            acc.x += x0.x * e0 + x1.x * e1 + x2.x * e2 + x3.x * e3;
            acc.y += x0.y * e0 + x1.y * e1 + x2.y * e2 + x3.y * e3;
        }
        for (; i < end; i++) {
            int s0 = g_csrc[i];
            float e0 = __expf(lrelu(g_as2[s0] + adv) - M2);
            float2 x0 = __half22float2(*(const __half2*)&g_xw2h[(size_t)s0 * HID + 2 * l]);
            den += e0;
            acc.x += x0.x * e0;
            acc.y += x0.y * e0;
        }
        float r = 1.f / den;
        float2 bb = ((const float2*)b2)[l];
        float ox = eluf(acc.x * r + bb.x);
        float oy = eluf(acc.y * r + bb.y);
        float2 wv = ((const float2*)Wout)[l];
        float p = ox * wv.x + oy * wv.y;
#pragma unroll
        for (int off = 16; off; off >>= 1) p += __shfl_xor_sync(0xffffffffu, p, off);
        float lg = p + bout[0];
        elg = __expf(lg);
        if (l == 0) { out[n + w] = lg; g_elg[w] = elg; }
    }
    if (l == 0) sm[wi] = elg;
    __syncthreads();
    if (threadIdx.x == 0) {
        float s = sm[0];
#pragma unroll
        for (int k = 1; k < 8; k++) s += sm[k];
        atomicAdd(&g_sumexp, s);
    }
}

__global__ void k_weights(float* __restrict__ out, int n) {
    int i = blockIdx.x * blockDim.x + threadIdx.x;
    if (i >= n) return;
    out[i] = g_elg[i] / g_sumexp;
}

// ------------------------- launch (two-stream fork/join) ----------------------
extern "C" void kernel_launch(void* const* d_in, const int* in_sizes, int n_in,
                              void* d_out, int out_size)
{
    const float* x    = (const float*)d_in[0];
    const int*   ei   = (const int*)d_in[1];
    const float* reg  = (const float*)d_in[2];
    const float* ng   = (const float*)d_in[3];
    const float* nb   = (const float*)d_in[4];
    const float* rg   = (const float*)d_in[5];
    const float* rb   = (const float*)d_in[6];
    const float* W1   = (const float*)d_in[7];
    const float* as1  = (const float*)d_in[8];
    const float* ad1  = (const float*)d_in[9];
    const float* b1   = (const float*)d_in[10];
    const float* W2   = (const float*)d_in[11];
    const float* as2  = (const float*)d_in[12];
    const float* ad2  = (const float*)d_in[13];
    const float* b2   = (const float*)d_in[14];
    const float* Wout = (const float*)d_in[15];
    const float* bout = (const float*)d_in[16];
    float* out = (float*)d_out;

    int n = in_sizes[0] / FIN;
    int e = in_sizes[1] / 2;
    int etot = e + n;
    int wb = (n + 7) / 8;
    int nbScan = (n + 1023) / 1024;
    int edgeB = (etot + 1023) / 1024;

    cudaStream_t sB;
    cudaStreamCreateWithFlags(&sB, cudaStreamNonBlocking);
    cudaEvent_t evFork, evJoin;
    cudaEventCreateWithFlags(&evFork, cudaEventDisableTiming);
    cudaEventCreateWithFlags(&evJoin, cudaEventDisableTiming);

    // fork: CSR chain on stream B (independent of compute chain until agg1)
    cudaEventRecord(evFork, 0);
    cudaStreamWaitEvent(sB, evFork, 0);
    k_count<<<edgeB, 256, 0, sB>>>(ei, e, etot);
    k_scanA<<<nbScan, 256, 0, sB>>>(n);
    k_scanC<<<nbScan, 256, 0, sB>>>(n, etot);
    k_scatter<<<edgeB, 256, 0, sB>>>(ei, e, etot);
    cudaEventRecord(evJoin, sB);

    // compute chain on main stream
    k_phase1a<<<wb + PWB + 1, 256>>>(x, ng, nb, reg, rg, rb, W1, W2, n, wb);
    int nGB = 2 * ((n + 127) / 128);
    k_hgemm1<<<nGB, 256>>>(W1, n);
    k_alpha1<<<wb, 256>>>(as1, ad1, n);

    // join: agg1 needs CSR + alpha1
    cudaStreamWaitEvent(0, evJoin, 0);
    k_agg1<<<wb, 256>>>(b1, n);

    dim3 g2(1, (n + 127) / 128);
    k_hgemm2_a2<<<g2, 256>>>(as2, ad2, n);
    k_agg2_logits<<<wb, 256>>>(b2, Wout, bout, out, n);
    k_weights<<<(n + 255) / 256, 256>>>(out, n);

    cudaEventDestroy(evFork);
    cudaEventDestroy(evJoin);
    cudaStreamDestroy(sB);
}